// round 11
// baseline (speedup 1.0000x reference)
#include <cuda_runtime.h>
#include <cuda_bf16.h>
#include <cstdint>
#include <stdint.h>
#include <math.h>
#include <string.h>

// ---------------- problem constants ----------------
#define NB     64
#define LL     512
#define NN     (NB*LL)   // 32768
#define SIZE   128
#define NBR    15
#define KER    16
#define DEPTH  3
#define EDGE   29
#define EPAD   32

// ---------------- scratch ----------------
__device__ float g_pos[NN*3];
__device__ float g_R[NN*9];
__device__ int   g_nbr[NN*NBR];
__device__ float g_edge[(size_t)NN*NBR*EPAD];
__device__ float g_h[NN*SIZE];
__device__ float g_qkv[NN*384];
__device__ float g_opre[NN*SIZE];
__device__ float g_res[NN*SIZE];
__device__ float g_hinit[SIZE];
__device__ float g_qkv0[384];
__device__ float g_xa[(size_t)NB*SIZE*LL];
__device__ float g_xb[(size_t)NB*SIZE*(LL/2)];
__device__ float g_cpart[(size_t)3*NB*SIZE*LL];   // conv shift partials (50 MB)
__device__ __nv_bfloat16 g_wtiles[21*32768];
__device__ __nv_bfloat16 g_ctiles[12*32768];

// ---------------- helpers ----------------
__device__ __forceinline__ uint32_t smem_u32(const void* p) {
    uint32_t a;
    asm("{ .reg .u64 t; cvta.to.shared.u64 t, %1; cvt.u32.u64 %0, t; }" : "=r"(a) : "l"(p));
    return a;
}
__device__ __forceinline__ uint32_t tile_off(int row, int k) {
    return (uint32_t)(row*256 + ((((k>>3) ^ (row&7)) & 15) << 4) + (k&7)*2);
}
__device__ __forceinline__ uint32_t frag_addr(uint32_t base, int row, int kc) {
    return base + row*256 + (((kc ^ (row&7)) & 15) << 4);
}
__device__ __forceinline__ void ldm_x4(uint32_t* r, uint32_t addr) {
    asm volatile("ldmatrix.sync.aligned.m8n8.x4.shared.b16 {%0,%1,%2,%3}, [%4];"
        : "=r"(r[0]), "=r"(r[1]), "=r"(r[2]), "=r"(r[3]) : "r"(addr));
}
__device__ __forceinline__ void mma16816(float* c, const uint32_t* a, const uint32_t* b) {
    asm volatile("mma.sync.aligned.m16n8k16.row.col.f32.bf16.bf16.f32 "
        "{%0,%1,%2,%3}, {%4,%5,%6,%7}, {%8,%9}, {%0,%1,%2,%3};"
        : "+f"(c[0]), "+f"(c[1]), "+f"(c[2]), "+f"(c[3])
        : "r"(a[0]), "r"(a[1]), "r"(a[2]), "r"(a[3]), "r"(b[0]), "r"(b[1]));
}
__device__ __forceinline__ void split_store(char* dsmp, uint32_t loOfs, int row, int col, float v0, float v1) {
    __nv_bfloat162 hi = __floats2bfloat162_rn(v0, v1);
    float r0 = v0 - __bfloat162float(__low2bfloat16(hi));
    float r1 = v1 - __bfloat162float(__high2bfloat16(hi));
    __nv_bfloat162 lo = __floats2bfloat162_rn(r0, r1);
    uint32_t off = tile_off(row, col);
    *(__nv_bfloat162*)(dsmp + off)         = hi;
    *(__nv_bfloat162*)(dsmp + loOfs + off) = lo;
}

// ---------------- geometry ----------------
__device__ __forceinline__ float3 pos_at(const float* t, int i) {
    return make_float3(t[i*9+3], t[i*9+4], t[i*9+5]);
}
__device__ __forceinline__ float3 vsub(float3 a, float3 b){ return make_float3(a.x-b.x,a.y-b.y,a.z-b.z); }
__device__ __forceinline__ float3 vcross(float3 a, float3 b){
    return make_float3(a.y*b.z-a.z*b.y, a.z*b.x-a.x*b.z, a.x*b.y-a.y*b.x);
}
__device__ __forceinline__ float3 vnorm(float3 v){
    float n = sqrtf(v.x*v.x+v.y*v.y+v.z*v.z) + 1e-8f;
    return make_float3(v.x/n, v.y/n, v.z/n);
}

// ---------------- K: frames ----------------
__global__ void k_frames(const float* __restrict__ tert, float* __restrict__ pos, float* __restrict__ R) {
    int i = blockIdx.x*blockDim.x + threadIdx.x;
    if (i >= NN) return;
    float3 pi = pos_at(tert, i);
    pos[i*3+0]=pi.x; pos[i*3+1]=pi.y; pos[i*3+2]=pi.z;
    int t1 = (i >= 1) ? (i-1) : 0;
    int t2 = (i <= NN-2) ? i : (NN-2);
    float3 up = vnorm(vsub(pos_at(tert, t1+1), pos_at(tert, t1)));
    float3 un = vnorm(vsub(pos_at(tert, t2+1), pos_at(tert, t2)));
    float3 b  = vnorm(vsub(up, un));
    float3 nv = vnorm(vcross(up, un));
    float3 c3 = vcross(b, nv);
    float* r = R + (size_t)i*9;
    r[0]=b.x; r[1]=nv.x; r[2]=c3.x;
    r[3]=b.y; r[4]=nv.y; r[5]=c3.y;
    r[6]=b.z; r[7]=nv.z; r[8]=c3.z;
}

// ---------------- K: top-k ----------------
__global__ void k_topk(const float* __restrict__ pos, const float* __restrict__ noise,
                       int* __restrict__ nbr) {
    int warp = (blockIdx.x*blockDim.x + threadIdx.x) >> 5;
    int lane = threadIdx.x & 31;
    if (warp >= NN) return;
    int b = warp >> 9;
    int i = warp & (LL-1);
    const float* pb = pos + (size_t)b*LL*3;
    float px = pb[i*3], py = pb[i*3+1], pz = pb[i*3+2];
    const float* nrow = noise + ((size_t)b*LL + i)*LL;
    float vals[16];
#pragma unroll
    for (int t = 0; t < 16; t++) {
        int j = lane + (t<<5);
        float dx = pb[j*3]-px, dy = pb[j*3+1]-py, dz = pb[j*3+2]-pz;
        float d = sqrtf(dx*dx+dy*dy+dz*dz);
        vals[t] = -d + 3.0f*nrow[j];
    }
    for (int r = 0; r < NBR; r++) {
        float bv = vals[0]; int bt = 0;
#pragma unroll
        for (int t = 1; t < 16; t++)
            if (vals[t] > bv) { bv = vals[t]; bt = t; }
        int bj = lane + (bt<<5);
#pragma unroll
        for (int off = 16; off; off >>= 1) {
            float ov = __shfl_xor_sync(0xffffffffu, bv, off);
            int   oj = __shfl_xor_sync(0xffffffffu, bj, off);
            if (ov > bv || (ov == bv && oj < bj)) { bv = ov; bj = oj; }
        }
        if (lane == (bj & 31)) {
            int slot = bj >> 5;
#pragma unroll
            for (int t = 0; t < 16; t++)
                if (t == slot) vals[t] = -3.402823466e38f;
        }
        if (lane == 0) nbr[warp*NBR + r] = b*LL + bj;
    }
}

// ---------------- K: edge features ----------------
__global__ __launch_bounds__(256)
void k_edge(const float* __restrict__ pos, const float* __restrict__ R,
            const int* __restrict__ nbr, float* __restrict__ edge) {
    __shared__ float se[256*33];
    int e0 = blockIdx.x*256;
    int e = e0 + threadIdx.x;
    int n = e / NBR;
    int m = nbr[e];
    float dx = pos[m*3]-pos[n*3], dy = pos[m*3+1]-pos[n*3+1], dz = pos[m*3+2]-pos[n*3+2];
    float d = sqrtf(dx*dx+dy*dy+dz*dz);
    float* row = se + threadIdx.x*33;
#pragma unroll
    for (int t = 0; t < KER; t++) {
        float mu = (20.0f/15.0f)*t;
        float r = (d - mu)*0.8f;
        row[t] = expf(-r*r);
    }
    float inv = 1.0f/(d + 1e-8f);
    float u0 = dx*inv, u1 = dy*inv, u2 = dz*inv;
    const float* Rn = R + (size_t)n*9;
    const float* Rm = R + (size_t)m*9;
#pragma unroll
    for (int c = 0; c < 3; c++)
        row[16+c] = Rn[0*3+c]*u0 + Rn[1*3+c]*u1 + Rn[2*3+c]*u2;
#pragma unroll
    for (int c = 0; c < 3; c++)
#pragma unroll
        for (int dd = 0; dd < 3; dd++)
            row[19 + c*3 + dd] = Rn[0*3+c]*Rm[0*3+dd] + Rn[1*3+c]*Rm[1*3+dd] + Rn[2*3+c]*Rm[2*3+dd];
    row[28] = (float)(m - n);
    row[29] = 0.f; row[30] = 0.f; row[31] = 0.f;
    __syncthreads();
    float* dst = edge + (size_t)e0*EPAD;
    for (int i = threadIdx.x; i < 256*EPAD; i += 256)
        dst[i] = se[(i >> 5)*33 + (i & 31)];
}

// ---------------- h init ----------------
__global__ void k_hinit(const float* __restrict__ ew, const float* __restrict__ eb,
                        float* __restrict__ hi) {
    int c = threadIdx.x;
    float s = eb[c];
    for (int i = 0; i < 27; i++) s += ew[i*SIZE + c];
    hi[c] = s;
}

// ---------------- layer-0 qkv vector ----------------
__global__ void k_qkv0(const float* __restrict__ hi, const float* __restrict__ wq,
                       const float* __restrict__ wk, const float* __restrict__ wv,
                       float* __restrict__ qkv0) {
    int c = threadIdx.x;
    const float* W = (c < 128) ? (wq + c) : (c < 256) ? (wk + (c-128)) : (wv + (c-256));
    float s = 0.0f;
    for (int k = 0; k < 128; k++) s += hi[k]*W[k*128];
    qkv0[c] = s;
}

// ---------------- weight packs ----------------
__global__ void k_pack_tiles(const float* __restrict__ wq, const float* __restrict__ wk,
                             const float* __restrict__ wv, const float* __restrict__ wo,
                             const float* __restrict__ w1, const float* __restrict__ w2,
                             const float* __restrict__ w3, __nv_bfloat16* __restrict__ tiles) {
    int t = blockIdx.x;
    int l = t / 7, w = t % 7;
    const float* src;
    switch (w) {
        case 0: src = wq + (size_t)l*128*128; break;
        case 1: src = wk + (size_t)l*157*128; break;
        case 2: src = wv + (size_t)l*157*128; break;
        case 3: src = wo + (size_t)l*128*128; break;
        case 4: src = w1 + (size_t)l*128*128; break;
        case 5: src = w2 + (size_t)l*128*128; break;
        default: src = w3 + (size_t)l*128*128; break;
    }
    char* dh = (char*)(tiles + (size_t)t*32768);
    char* dl = dh + 32768;
    int e0 = blockIdx.y*2048;
    for (int e = e0 + threadIdx.x; e < e0 + 2048; e += 256) {
        int p = e & 127, k = e >> 7;
        float x = src[k*128 + p];
        __nv_bfloat16 h = __float2bfloat16(x);
        __nv_bfloat16 lo = __float2bfloat16(x - __bfloat162float(h));
        uint32_t off = tile_off(p, k);
        *(__nv_bfloat16*)(dh + off) = h;
        *(__nv_bfloat16*)(dl + off) = lo;
    }
}

__global__ void k_pack_conv(const float* __restrict__ pw, __nv_bfloat16* __restrict__ ct) {
    int t = blockIdx.x;
    int layer = t / 3, k = t % 3;
    const float* src = pw + (size_t)layer*128*128*3;
    char* dh = (char*)(ct + (size_t)t*32768);
    char* dl = dh + 32768;
    int e0 = blockIdx.y*2048;
    for (int e = e0 + threadIdx.x; e < e0 + 2048; e += 256) {
        int o = e >> 7, i = e & 127;
        float x = src[o*384 + i*3 + k];
        __nv_bfloat16 h = __float2bfloat16(x);
        __nv_bfloat16 lo = __float2bfloat16(x - __bfloat162float(h));
        uint32_t off = tile_off(o, i);
        *(__nv_bfloat16*)(dh + off) = h;
        *(__nv_bfloat16*)(dl + off) = lo;
    }
}

// ---------------- fused transformer layer (+ optional next-layer QKV) ----------------
// stages 0..3: wo(+res), w1(relu), w2(relu), w3(+res) -> h
// stages 4..6 (if qkv_out): next layer's wq,wk,wv on the new h -> qkv
__global__ __launch_bounds__(256, 2)
void k_layer(const float* __restrict__ opre, float* __restrict__ h,
             float* __restrict__ res, const __nv_bfloat16* __restrict__ lt,
             const __nv_bfloat16* __restrict__ ltn,
             const float* __restrict__ b1, const float* __restrict__ b2,
             const float* __restrict__ b3, const float* __restrict__ hvec,
             float* __restrict__ qkv_out) {
    extern __shared__ char dsm[];
    const uint32_t base = smem_u32(dsm);
    const uint32_t AH = base, AL = base + 32768, BB = base + 65536;

    int tid = threadIdx.x, lane = tid & 31, wid = tid >> 5;
    int row0 = blockIdx.x*128;
    int nstages = qkv_out ? 7 : 4;

    {
        const float* Arow = opre + (size_t)row0*128;
        for (int e = tid*4; e < 16384; e += 1024) {
            int r = e >> 7, k = e & 127;
            float4 a4 = *(const float4*)(Arow + r*128 + k);
            split_store(dsm, 32768, r, k,   a4.x, a4.y);
            split_store(dsm, 32768, r, k+2, a4.z, a4.w);
        }
    }

    int m_base = (wid & 3)*32, n_base = (wid >> 2)*64;
    int a_m  = (lane & 15);
    int a_kc = (lane >> 4);
    int b_r  = (lane & 7);
    int b_g  = (lane >> 3);
    int b_na = ((b_g >> 1) << 3) + b_r;
    int b_ka = (b_g & 1);
    int qr = lane >> 2, qc = (lane & 3)*2;

    for (int s = 0; s < nstages; s++) {
        const __nv_bfloat16* wtile = (s < 4) ? (lt + (size_t)(3 + s)*32768)
                                             : (ltn + (size_t)(s - 4)*32768);
        __syncthreads();
        {
            const uint4* src = (const uint4*)wtile;
            uint4* dst = (uint4*)(dsm + 65536);
            for (int i = tid; i < 2048; i += 256) dst[i] = src[i];
        }
        __syncthreads();

        float acc[2][8][4];
#pragma unroll
        for (int mt = 0; mt < 2; mt++)
#pragma unroll
            for (int nt = 0; nt < 8; nt++)
#pragma unroll
                for (int c = 0; c < 4; c++) acc[mt][nt][c] = 0.0f;

#pragma unroll
        for (int ks = 0; ks < 8; ks++) {
            int kc0 = ks*2;
            uint32_t ah[2][4], al[2][4];
#pragma unroll
            for (int mt = 0; mt < 2; mt++) {
                int m = m_base + mt*16 + a_m;
                ldm_x4(ah[mt], frag_addr(AH, m, kc0 + a_kc));
                ldm_x4(al[mt], frag_addr(AL, m, kc0 + a_kc));
            }
            uint32_t bb[4][4];
#pragma unroll
            for (int p = 0; p < 4; p++) {
                int n = n_base + p*16 + b_na;
                ldm_x4(bb[p], frag_addr(BB, n, kc0 + b_ka));
            }
#pragma unroll
            for (int mt = 0; mt < 2; mt++)
#pragma unroll
                for (int nt = 0; nt < 8; nt++) {
                    mma16816(acc[mt][nt], ah[mt], &bb[nt>>1][(nt&1)*2]);
                    mma16816(acc[mt][nt], al[mt], &bb[nt>>1][(nt&1)*2]);
                }
        }

        __syncthreads();
        {
            const uint4* src = (const uint4*)(wtile + 16384);
            uint4* dst = (uint4*)(dsm + 65536);
            for (int i = tid; i < 2048; i += 256) dst[i] = src[i];
        }
        __syncthreads();

#pragma unroll
        for (int ks = 0; ks < 8; ks++) {
            int kc0 = ks*2;
            uint32_t ah[2][4];
#pragma unroll
            for (int mt = 0; mt < 2; mt++) {
                int m = m_base + mt*16 + a_m;
                ldm_x4(ah[mt], frag_addr(AH, m, kc0 + a_kc));
            }
            uint32_t bb[4][4];
#pragma unroll
            for (int p = 0; p < 4; p++) {
                int n = n_base + p*16 + b_na;
                ldm_x4(bb[p], frag_addr(BB, n, kc0 + b_ka));
            }
#pragma unroll
            for (int mt = 0; mt < 2; mt++)
#pragma unroll
                for (int nt = 0; nt < 8; nt++)
                    mma16816(acc[mt][nt], ah[mt], &bb[nt>>1][(nt&1)*2]);
        }

        __syncthreads();

        const float* bias = (s == 1) ? b1 : (s == 2) ? b2 : (s == 3) ? b3 : nullptr;
#pragma unroll
        for (int mt = 0; mt < 2; mt++) {
#pragma unroll
            for (int hh = 0; hh < 2; hh++) {
                int rl = m_base + mt*16 + qr + hh*8;
                int row = row0 + rl;
#pragma unroll
                for (int nt = 0; nt < 8; nt++) {
                    int cc = n_base + nt*8 + qc;
                    float v0 = acc[mt][nt][hh*2+0];
                    float v1 = acc[mt][nt][hh*2+1];
                    if (s == 0) {
                        if (hvec) { v0 += hvec[cc]; v1 += hvec[cc+1]; }
                        else {
                            float2 h2 = *(const float2*)(h + (size_t)row*128 + cc);
                            v0 += h2.x; v1 += h2.y;
                        }
                        *(float2*)(res + (size_t)row*128 + cc) = make_float2(v0, v1);
                        split_store(dsm, 32768, rl, cc, v0, v1);
                    } else if (s < 3) {
                        v0 = fmaxf(v0 + bias[cc], 0.f);
                        v1 = fmaxf(v1 + bias[cc+1], 0.f);
                        split_store(dsm, 32768, rl, cc, v0, v1);
                    } else if (s == 3) {
                        float2 r2 = *(const float2*)(res + (size_t)row*128 + cc);
                        v0 += bias[cc]   + r2.x;
                        v1 += bias[cc+1] + r2.y;
                        *(float2*)(h + (size_t)row*128 + cc) = make_float2(v0, v1);
                        if (nstages > 4) split_store(dsm, 32768, rl, cc, v0, v1);
                    } else {
                        float* crow = qkv_out + (size_t)row*384 + (s-4)*128;
                        *(float2*)(crow + cc) = make_float2(v0, v1);
                    }
                }
            }
        }
    }
}

// ---------------- conv via tensor cores: one shift per CTA, partial y out ----------------
__global__ __launch_bounds__(256, 2)
void k_conv_mma(const float* __restrict__ x, const __nv_bfloat16* __restrict__ ctiles,
                float* __restrict__ part, int Lin) {
    extern __shared__ char dsm[];
    const uint32_t base = smem_u32(dsm);
    const uint32_t AH = base, AL = base + 33792, BB = base + 67584;

    int tid = threadIdx.x, lane = tid & 31, wid = tid >> 5;
    int b = blockIdx.y, t0 = blockIdx.x*128, sh = blockIdx.z;
    const float* xb = x + (size_t)b*128*Lin;
    const __nv_bfloat16* wt = ctiles + (size_t)sh*32768;

    {
        int c = tid >> 1, half = tid & 1;
        const float* xrow = xb + (size_t)c*Lin;
        for (int tp = half*66; tp < half*66 + 66; tp++) {
            int t = t0 + tp - 1;
            float v = (tp < 130 && t >= 0 && t < Lin) ? xrow[t] : 0.0f;
            __nv_bfloat16 hh = __float2bfloat16(v);
            __nv_bfloat16 ll = __float2bfloat16(v - __bfloat162float(hh));
            uint32_t off = tile_off(tp, c);
            *(__nv_bfloat16*)(dsm + off)         = hh;
            *(__nv_bfloat16*)(dsm + 33792 + off) = ll;
        }
    }
    {
        const uint4* src = (const uint4*)wt;
        uint4* dst = (uint4*)(dsm + 67584);
        for (int i = tid; i < 2048; i += 256) dst[i] = src[i];
    }
    __syncthreads();

    int m_base = (wid & 3)*32, n_base = (wid >> 2)*64;
    float acc[2][8][4];
#pragma unroll
    for (int mt = 0; mt < 2; mt++)
#pragma unroll
        for (int nt = 0; nt < 8; nt++)
#pragma unroll
            for (int c = 0; c < 4; c++) acc[mt][nt][c] = 0.0f;

    int a_m  = (lane & 15);
    int a_kc = (lane >> 4);
    int b_r  = (lane & 7);
    int b_g  = (lane >> 3);
    int b_na = ((b_g >> 1) << 3) + b_r;
    int b_ka = (b_g & 1);

    // merged pass (Ah + Al) x Bh
#pragma unroll
    for (int ks = 0; ks < 8; ks++) {
        int kc0 = ks*2;
        uint32_t ah[2][4], al[2][4];
#pragma unroll
        for (int mt = 0; mt < 2; mt++) {
            int m = m_base + mt*16 + a_m + sh;
            ldm_x4(ah[mt], frag_addr(AH, m, kc0 + a_kc));
            ldm_x4(al[mt], frag_addr(AL, m, kc0 + a_kc));
        }
        uint32_t bb[4][4];
#pragma unroll
        for (int p = 0; p < 4; p++) {
            int n = n_base + p*16 + b_na;
            ldm_x4(bb[p], frag_addr(BB, n, kc0 + b_ka));
        }
#pragma unroll
        for (int mt = 0; mt < 2; mt++)
#pragma unroll
            for (int nt = 0; nt < 8; nt++) {
                mma16816(acc[mt][nt], ah[mt], &bb[nt>>1][(nt&1)*2]);
                mma16816(acc[mt][nt], al[mt], &bb[nt>>1][(nt&1)*2]);
            }
    }
    __syncthreads();
    {
        const uint4* src = (const uint4*)(wt + 16384);
        uint4* dst = (uint4*)(dsm + 67584);
        for (int i = tid; i < 2048; i += 256) dst[i] = src[i];
    }
    __syncthreads();
    // pass Ah x Bl
#pragma unroll
    for (int ks = 0; ks < 8; ks++) {
        int kc0 = ks*2;
        uint32_t ah[2][4];
#pragma unroll
        for (int mt = 0; mt < 2; mt++) {
            int m = m_base + mt*16 + a_m + sh;
            ldm_x4(ah[mt], frag_addr(AH, m, kc0 + a_kc));
        }
        uint32_t bb[4][4];
#pragma unroll
        for (int p = 0; p < 4; p++) {
            int n = n_base + p*16 + b_na;
            ldm_x4(bb[p], frag_addr(BB, n, kc0 + b_ka));
        }
#pragma unroll
        for (int mt = 0; mt < 2; mt++)
#pragma unroll
            for (int nt = 0; nt < 8; nt++)
                mma16816(acc[mt][nt], ah[mt], &bb[nt>>1][(nt&1)*2]);
    }

    __syncthreads();
    float* ys = (float*)dsm;   // [o][t] stride 132
    int qr = lane >> 2, qc = (lane & 3)*2;
#pragma unroll
    for (int mt = 0; mt < 2; mt++)
#pragma unroll
        for (int h = 0; h < 2; h++) {
            int m = m_base + mt*16 + h*8 + qr;
#pragma unroll
            for (int nt = 0; nt < 8; nt++) {
                int n0 = n_base + nt*8 + qc;
                ys[(size_t)n0*132 + m]     = acc[mt][nt][h*2+0];
                ys[(size_t)(n0+1)*132 + m] = acc[mt][nt][h*2+1];
            }
        }
    __syncthreads();

    {
        int o = tid >> 1, half = tid & 1;
        int Mrows = (Lin - t0 < 128) ? (Lin - t0) : 128;
        float* prow = part + (((size_t)sh*NB + b)*128 + o)*Lin + t0;
        for (int t = half*64; t < Mrows && t < half*64 + 64; t++)
            prow[t] = ys[(size_t)o*132 + t];
    }
}

// ---------------- conv epilogue: sum partials + bias + leaky + residual + maxpool ----------------
__global__ __launch_bounds__(256)
void k_conv_epi(const float* __restrict__ x, const float* __restrict__ part,
                const float* __restrict__ bias, float* __restrict__ out, int Lin) {
    int idx = blockIdx.x*256 + threadIdx.x;
    int half = Lin >> 1;
    int th = idx % half;
    int oc = (idx / half) & 127;
    int b  = idx / (half*128);
    size_t S = (size_t)NB*128*Lin;
    size_t bse = ((size_t)b*128 + oc)*Lin + 2*th;
    float bo = bias[oc];
    float y0 = part[bse]   + part[S+bse]   + part[2*S+bse]   + bo;
    float y1 = part[bse+1] + part[S+bse+1] + part[2*S+bse+1] + bo;
    float x0 = x[bse], x1 = x[bse+1];
    float z0 = x0 + (y0 > 0.f ? y0 : 0.01f*y0);
    float z1 = x1 + (y1 > 0.f ? y1 : 0.01f*y1);
    out[((size_t)b*128 + oc)*half + th] = fmaxf(z0, z1);
}

// ---------------- attention layer 0 ----------------
__global__ __launch_bounds__(256)
void k_attn0(const float* __restrict__ qkv0, const float* __restrict__ edge,
             const float* __restrict__ wk_e, const float* __restrict__ wv_e,
             float* __restrict__ opre) {
    __shared__ __align__(16) float sWk[EDGE*128];
    __shared__ __align__(16) float sWv[EDGE*128];
    __shared__ __align__(16) float sE[8][NBR*EPAD];

    int tid = threadIdx.x;
    for (int idx = tid; idx < EDGE*128; idx += 256) {
        sWk[idx] = wk_e[idx];
        sWv[idx] = wv_e[idx];
    }
    __syncthreads();

    int w = tid >> 5, lane = tid & 31;
    int n = blockIdx.x*8 + w;
    int d0 = lane*4;

    float4 q4 = *(const float4*)(qkv0 + d0);
    float4 v04 = *(const float4*)(qkv0 + 256 + d0);

    float qeh[EPAD];
#pragma unroll
    for (int e = 0; e < EDGE; e++) {
        float4 w4 = *(const float4*)(&sWk[e*128 + d0]);
        float p = q4.x*w4.x + q4.y*w4.y + q4.z*w4.z + q4.w*w4.w;
        p += __shfl_xor_sync(0xffffffffu, p, 1);
        p += __shfl_xor_sync(0xffffffffu, p, 2);
        qeh[e] = p;
    }
    qeh[29] = 0.f; qeh[30] = 0.f; qeh[31] = 0.f;

    {
        const float4* er4 = (const float4*)(edge + (size_t)n*NBR*EPAD);
        float4* sE4 = (float4*)sE[w];
        for (int idx = lane; idx < NBR*(EPAD/4); idx += 32) sE4[idx] = er4[idx];
    }
    __syncwarp();

    float logits[NBR];
#pragma unroll
    for (int j = 0; j < NBR; j++) {
        const float4* se = (const float4*)(sE[w] + j*EPAD);
        float e0 = 0.f, e1 = 0.f, e2 = 0.f, e3 = 0.f;
#pragma unroll
        for (int q = 0; q < 8; q++) {
            float4 s = se[q];
            e0 += s.x*qeh[q*4+0];
            e1 += s.y*qeh[q*4+1];
            e2 += s.z*qeh[q*4+2];
            e3 += s.w*qeh[q*4+3];
        }
        logits[j] = ((e0+e1)+(e2+e3))*0.25f;
    }

    float mx = logits[0];
#pragma unroll
    for (int j = 1; j < NBR; j++) mx = fmaxf(mx, logits[j]);
    float s = 0.0f;
#pragma unroll
    for (int j = 0; j < NBR; j++) { logits[j] = expf(logits[j]-mx); s += logits[j]; }
    float invs = 1.0f/s;

    float4 ae4[8];
#pragma unroll
    for (int q = 0; q < 8; q++) ae4[q] = make_float4(0.f,0.f,0.f,0.f);

#pragma unroll
    for (int j = 0; j < NBR; j++) {
        float a = logits[j]*invs;
        const float4* se = (const float4*)(sE[w] + j*EPAD);
#pragma unroll
        for (int q = 0; q < 8; q++) {
            float4 sv = se[q];
            ae4[q].x += a*sv.x; ae4[q].y += a*sv.y;
            ae4[q].z += a*sv.z; ae4[q].w += a*sv.w;
        }
    }
    float4 acc = v04;
#pragma unroll
    for (int q = 0; q < 8; q++) {
#pragma unroll
        for (int c2 = 0; c2 < 4; c2++) {
            int e = q*4 + c2;
            if (e >= EDGE) continue;
            float aev = (c2 == 0) ? ae4[q].x : (c2 == 1) ? ae4[q].y : (c2 == 2) ? ae4[q].z : ae4[q].w;
            float4 w4 = *(const float4*)(&sWv[e*128 + d0]);
            acc.x += aev*w4.x; acc.y += aev*w4.y;
            acc.z += aev*w4.z; acc.w += aev*w4.w;
        }
    }
    *(float4*)(opre + (size_t)n*SIZE + d0) = acc;
}

// ---------------- attention (layers 1+) ----------------
__global__ __launch_bounds__(256)
void k_attn(const float* __restrict__ qkv, const float* __restrict__ edge,
            const int* __restrict__ nbr,
            const float* __restrict__ wk_e, const float* __restrict__ wv_e,
            float* __restrict__ opre) {
    __shared__ __align__(16) float sWk[EDGE*128];
    __shared__ __align__(16) float sWv[EDGE*128];
    __shared__ __align__(16) float sE[8][NBR*EPAD];

    int tid = threadIdx.x;
    for (int idx = tid; idx < EDGE*128; idx += 256) {
        sWk[idx] = wk_e[idx];
        sWv[idx] = wv_e[idx];
    }
    __syncthreads();

    int w = tid >> 5, lane = tid & 31;
    int n = blockIdx.x*8 + w;
    int d0 = lane*4;

    float4 q4 = *(const float4*)(qkv + (size_t)n*384 + d0);

    float qeh[EPAD];
#pragma unroll
    for (int e = 0; e < EDGE; e++) {
        float4 w4 = *(const float4*)(&sWk[e*128 + d0]);
        float p = q4.x*w4.x + q4.y*w4.y + q4.z*w4.z + q4.w*w4.w;
        p += __shfl_xor_sync(0xffffffffu, p, 1);
        p += __shfl_xor_sync(0xffffffffu, p, 2);
        qeh[e] = p;
    }
    qeh[29] = 0.f; qeh[30] = 0.f; qeh[31] = 0.f;

    {
        const float4* er4 = (const float4*)(edge + (size_t)n*NBR*EPAD);
        float4* sE4 = (float4*)sE[w];
        for (int idx = lane; idx < NBR*(EPAD/4); idx += 32) sE4[idx] = er4[idx];
    }
    __syncwarp();

    const int* nb = nbr + n*NBR;
    int mj[NBR];
#pragma unroll
    for (int j = 0; j < NBR; j++) mj[j] = nb[j];

    float logits[NBR];
#pragma unroll
    for (int j = 0; j < NBR; j++) {
        float4 k4 = *(const float4*)(qkv + (size_t)mj[j]*384 + 128 + d0);
        float p = q4.x*k4.x + q4.y*k4.y + q4.z*k4.z + q4.w*k4.w;
        p += __shfl_xor_sync(0xffffffffu, p, 1);
        p += __shfl_xor_sync(0xffffffffu, p, 2);
        const float4* se = (const float4*)(sE[w] + j*EPAD);
        float e0 = 0.f, e1 = 0.f, e2 = 0.f, e3 = 0.f;
#pragma unroll
        for (int q = 0; q < 8; q++) {
            float4 s = se[q];
            e0 += s.x*qeh[q*4+0];
            e1 += s.y*qeh[q*4+1];
            e2 += s.z*qeh[q*4+2];
            e3 += s.w*qeh[q*4+3];
        }
        logits[j] = (p + ((e0+e1)+(e2+e3)))*0.25f;
    }

    float mx = logits[0];
#pragma unroll
    for (int j = 1; j < NBR; j++) mx = fmaxf(mx, logits[j]);
    float s = 0.0f;
#pragma unroll
    for (int j = 0; j < NBR; j++) { logits[j] = expf(logits[j]-mx); s += logits[j]; }
    float invs = 1.0f/s;

    float4 ae4[8];
#pragma unroll
    for (int q = 0; q < 8; q++) ae4[q] = make_float4(0.f,0.f,0.f,0.f);

    float4 acc = make_float4(0.f,0.f,0.f,0.f);
#pragma unroll
    for (int j = 0; j < NBR; j++) {
        float a = logits[j]*invs;
        float4 v4 = *(const float4*)(qkv + (size_t)mj[j]*384 + 256 + d0);
        acc.x += a*v4.x; acc.y += a*v4.y; acc.z += a*v4.z; acc.w += a*v4.w;
        const float4* se = (const float4*)(sE[w] + j*EPAD);
#pragma unroll
        for (int q = 0; q < 8; q++) {
            float4 sv = se[q];
            ae4[q].x += a*sv.x; ae4[q].y += a*sv.y;
            ae4[q].z += a*sv.z; ae4[q].w += a*sv.w;
        }
    }
#pragma unroll
    for (int q = 0; q < 8; q++) {
#pragma unroll
        for (int c2 = 0; c2 < 4; c2++) {
            int e = q*4 + c2;
            if (e >= EDGE) continue;
            float aev = (c2 == 0) ? ae4[q].x : (c2 == 1) ? ae4[q].y : (c2 == 2) ? ae4[q].z : ae4[q].w;
            float4 w4 = *(const float4*)(&sWv[e*128 + d0]);
            acc.x += aev*w4.x; acc.y += aev*w4.y;
            acc.z += aev*w4.z; acc.w += aev*w4.w;
        }
    }
    *(float4*)(opre + (size_t)n*SIZE + d0) = acc;
}

// ---------------- transpose ----------------
__global__ void k_transpose(const float* __restrict__ h, float* __restrict__ x) {
    int idx = blockIdx.x*blockDim.x + threadIdx.x;
    if (idx >= NN*SIZE) return;
    int t = idx & (LL-1);
    int c = (idx >> 9) & (SIZE-1);
    int b = idx >> 16;
    x[idx] = h[((size_t)(b*LL + t))*SIZE + c];
}

// ---------------- energy ----------------
__global__ void k_energy(const float* __restrict__ x, const float* __restrict__ ew,
                         const float* __restrict__ eb, float* __restrict__ out) {
    int b = blockIdx.x;
    int c = threadIdx.x;
    const float* xb = x + ((size_t)b*128 + c)*32;
    float s = 0.0f;
#pragma unroll
    for (int t = 0; t < 32; t++) s += xb[t];
    float v = s * ew[c];
    __shared__ float red[128];
    red[c] = v;
    __syncthreads();
    for (int st = 64; st; st >>= 1) {
        if (c < st) red[c] += red[c+st];
        __syncthreads();
    }
    if (c == 0) out[b] = red[0] + eb[0];
}

// ---------------- launch ----------------
extern "C" void kernel_launch(void* const* d_in, const int* in_sizes, int n_in,
                              void* d_out, int out_size) {
    const float* tert    = (const float*)d_in[0];
    const float* noise   = (const float*)d_in[3];
    const float* embed_w = (const float*)d_in[4];
    const float* embed_b = (const float*)d_in[5];
    const float* wq      = (const float*)d_in[6];
    const float* wk      = (const float*)d_in[7];
    const float* wv      = (const float*)d_in[8];
    const float* wo      = (const float*)d_in[9];
    const float* w1      = (const float*)d_in[10];
    const float* b1      = (const float*)d_in[11];
    const float* w2      = (const float*)d_in[12];
    const float* b2      = (const float*)d_in[13];
    const float* w3      = (const float*)d_in[14];
    const float* b3      = (const float*)d_in[15];
    const float* pool_w  = (const float*)d_in[16];
    const float* pool_b  = (const float*)d_in[17];
    const float* ew      = (const float*)d_in[18];
    const float* ebias   = (const float*)d_in[19];
    float* out = (float*)d_out;

    float *pos, *R, *edge, *h, *qkv, *opre, *res, *hi, *qkv0, *xa, *xb, *cpart;
    int *nbrp;
    __nv_bfloat16 *tiles, *ctiles;
    cudaGetSymbolAddress((void**)&pos,  g_pos);
    cudaGetSymbolAddress((void**)&R,    g_R);
    cudaGetSymbolAddress((void**)&nbrp, g_nbr);
    cudaGetSymbolAddress((void**)&edge, g_edge);
    cudaGetSymbolAddress((void**)&h,    g_h);
    cudaGetSymbolAddress((void**)&qkv,  g_qkv);
    cudaGetSymbolAddress((void**)&opre, g_opre);
    cudaGetSymbolAddress((void**)&res,  g_res);
    cudaGetSymbolAddress((void**)&hi,   g_hinit);
    cudaGetSymbolAddress((void**)&qkv0, g_qkv0);
    cudaGetSymbolAddress((void**)&xa,   g_xa);
    cudaGetSymbolAddress((void**)&xb,   g_xb);
    cudaGetSymbolAddress((void**)&cpart, g_cpart);
    cudaGetSymbolAddress((void**)&tiles,  g_wtiles);
    cudaGetSymbolAddress((void**)&ctiles, g_ctiles);

    const int GEMM_SMEM = 98304;
    const int CONV_SMEM = 100352;
    cudaFuncSetAttribute(k_layer,    cudaFuncAttributeMaxDynamicSharedMemorySize, GEMM_SMEM);
    cudaFuncSetAttribute(k_conv_mma, cudaFuncAttributeMaxDynamicSharedMemorySize, CONV_SMEM);

    k_frames<<<NN/256, 256>>>(tert, pos, R);
    k_topk<<<NN/8, 256>>>(pos, noise, nbrp);
    k_hinit<<<1, 128>>>(embed_w, embed_b, hi);
    k_edge<<<(NN*NBR)/256, 256>>>(pos, R, nbrp, edge);     // sampled (#4)
    k_pack_tiles<<<dim3(21,8), 256>>>(wq, wk, wv, wo, w1, w2, w3, tiles);
    k_pack_conv<<<dim3(12,8), 256>>>(pool_w, ctiles);
    k_qkv0<<<1, 384>>>(hi, wq, wk, wv, qkv0);

    // layer 0 (q/k/v identical across nodes) + next-layer QKV folded in
    {
        const float* wk_e = wk + 128*128;
        const float* wv_e = wv + 128*128;
        k_attn0<<<NN/8, 256>>>(qkv0, edge, wk_e, wv_e, opre);
        k_layer<<<NN/128, 256, GEMM_SMEM>>>(opre, h, res, tiles, tiles + 7*32768,
                                            b1, b2, b3, hi, qkv);
    }
    // layers 1..2
    for (int l = 1; l < DEPTH; l++) {
        const float* wk_e = wk + (size_t)l*157*128 + 128*128;
        const float* wv_e = wv + (size_t)l*157*128 + 128*128;
        const __nv_bfloat16* lt  = tiles + (size_t)l*7*32768;
        const __nv_bfloat16* ltn = tiles + (size_t)(l+1)*7*32768;   // unused when qkv_out null
        k_attn<<<NN/8, 256>>>(qkv, edge, nbrp, wk_e, wv_e, opre);
        k_layer<<<NN/128, 256, GEMM_SMEM>>>(opre, h, res, lt,
                                            (l < DEPTH-1) ? ltn : lt,
                                            b1 + l*128, b2 + l*128, b3 + l*128, nullptr,
                                            (l < DEPTH-1) ? qkv : nullptr);
    }

    k_transpose<<<NN*SIZE/256, 256>>>(h, xa);
    // conv: shift-split partials + epilogue
    k_conv_mma<<<dim3(4, NB, 3), 256, CONV_SMEM>>>(xa, ctiles + 0*3*32768, cpart, 512);
    k_conv_epi<<<(NB*128*256)/256, 256>>>(xa, cpart, pool_b + 0, xb, 512);
    k_conv_mma<<<dim3(2, NB, 3), 256, CONV_SMEM>>>(xb, ctiles + 1*3*32768, cpart, 256);
    k_conv_epi<<<(NB*128*128)/256, 256>>>(xb, cpart, pool_b + 128, xa, 256);
    k_conv_mma<<<dim3(1, NB, 3), 256, CONV_SMEM>>>(xa, ctiles + 2*3*32768, cpart, 128);
    k_conv_epi<<<(NB*128*64)/256, 256>>>(xa, cpart, pool_b + 256, xb, 128);
    k_conv_mma<<<dim3(1, NB, 3), 256, CONV_SMEM>>>(xb, ctiles + 3*3*32768, cpart, 64);
    k_conv_epi<<<(NB*128*32)/256, 256>>>(xb, cpart, pool_b + 384, xa, 64);
    k_energy<<<NB, 128>>>(xa, ew, ebias, out);
}

// round 12
// speedup vs baseline: 1.0755x; 1.0755x over previous
#include <cuda_runtime.h>
#include <cuda_bf16.h>
#include <cstdint>
#include <stdint.h>
#include <math.h>
#include <string.h>

// ---------------- problem constants ----------------
#define NB     64
#define LL     512
#define NN     (NB*LL)   // 32768
#define SIZE   128
#define NBR    15
#define KER    16
#define DEPTH  3
#define EDGE   29
#define EPAD   32

// ---------------- scratch ----------------
__device__ float g_pos[NN*3];
__device__ float g_R[NN*9];
__device__ int   g_nbr[NN*NBR];
__device__ float g_edge[(size_t)NN*NBR*EPAD];
__device__ float g_h[NN*SIZE];
__device__ float g_qkv[NN*384];
__device__ float g_opre[NN*SIZE];
__device__ float g_res[NN*SIZE];
__device__ float g_hinit[SIZE];
__device__ float g_qkv0[384];
__device__ float g_xa[(size_t)NB*SIZE*LL];
__device__ float g_xb[(size_t)NB*SIZE*(LL/2)];
__device__ __nv_bfloat16 g_wtiles[21*32768];
__device__ __nv_bfloat16 g_ctiles[12*32768];

// ---------------- helpers ----------------
__device__ __forceinline__ uint32_t smem_u32(const void* p) {
    uint32_t a;
    asm("{ .reg .u64 t; cvta.to.shared.u64 t, %1; cvt.u32.u64 %0, t; }" : "=r"(a) : "l"(p));
    return a;
}
__device__ __forceinline__ uint32_t tile_off(int row, int k) {
    return (uint32_t)(row*256 + ((((k>>3) ^ (row&7)) & 15) << 4) + (k&7)*2);
}
__device__ __forceinline__ uint32_t frag_addr(uint32_t base, int row, int kc) {
    return base + row*256 + (((kc ^ (row&7)) & 15) << 4);
}
__device__ __forceinline__ void ldm_x4(uint32_t* r, uint32_t addr) {
    asm volatile("ldmatrix.sync.aligned.m8n8.x4.shared.b16 {%0,%1,%2,%3}, [%4];"
        : "=r"(r[0]), "=r"(r[1]), "=r"(r[2]), "=r"(r[3]) : "r"(addr));
}
__device__ __forceinline__ void mma16816(float* c, const uint32_t* a, const uint32_t* b) {
    asm volatile("mma.sync.aligned.m16n8k16.row.col.f32.bf16.bf16.f32 "
        "{%0,%1,%2,%3}, {%4,%5,%6,%7}, {%8,%9}, {%0,%1,%2,%3};"
        : "+f"(c[0]), "+f"(c[1]), "+f"(c[2]), "+f"(c[3])
        : "r"(a[0]), "r"(a[1]), "r"(a[2]), "r"(a[3]), "r"(b[0]), "r"(b[1]));
}
__device__ __forceinline__ void split_store(char* dsmp, uint32_t loOfs, int row, int col, float v0, float v1) {
    __nv_bfloat162 hi = __floats2bfloat162_rn(v0, v1);
    float r0 = v0 - __bfloat162float(__low2bfloat16(hi));
    float r1 = v1 - __bfloat162float(__high2bfloat16(hi));
    __nv_bfloat162 lo = __floats2bfloat162_rn(r0, r1);
    uint32_t off = tile_off(row, col);
    *(__nv_bfloat162*)(dsmp + off)         = hi;
    *(__nv_bfloat162*)(dsmp + loOfs + off) = lo;
}

// ---------------- geometry ----------------
__device__ __forceinline__ float3 pos_at(const float* t, int i) {
    return make_float3(t[i*9+3], t[i*9+4], t[i*9+5]);
}
__device__ __forceinline__ float3 vsub(float3 a, float3 b){ return make_float3(a.x-b.x,a.y-b.y,a.z-b.z); }
__device__ __forceinline__ float3 vcross(float3 a, float3 b){
    return make_float3(a.y*b.z-a.z*b.y, a.z*b.x-a.x*b.z, a.x*b.y-a.y*b.x);
}
__device__ __forceinline__ float3 vnorm(float3 v){
    float n = sqrtf(v.x*v.x+v.y*v.y+v.z*v.z) + 1e-8f;
    return make_float3(v.x/n, v.y/n, v.z/n);
}

// ---------------- K: frames ----------------
__global__ void k_frames(const float* __restrict__ tert, float* __restrict__ pos, float* __restrict__ R) {
    int i = blockIdx.x*blockDim.x + threadIdx.x;
    if (i >= NN) return;
    float3 pi = pos_at(tert, i);
    pos[i*3+0]=pi.x; pos[i*3+1]=pi.y; pos[i*3+2]=pi.z;
    int t1 = (i >= 1) ? (i-1) : 0;
    int t2 = (i <= NN-2) ? i : (NN-2);
    float3 up = vnorm(vsub(pos_at(tert, t1+1), pos_at(tert, t1)));
    float3 un = vnorm(vsub(pos_at(tert, t2+1), pos_at(tert, t2)));
    float3 b  = vnorm(vsub(up, un));
    float3 nv = vnorm(vcross(up, un));
    float3 c3 = vcross(b, nv);
    float* r = R + (size_t)i*9;
    r[0]=b.x; r[1]=nv.x; r[2]=c3.x;
    r[3]=b.y; r[4]=nv.y; r[5]=c3.y;
    r[6]=b.z; r[7]=nv.z; r[8]=c3.z;
}

// ---------------- K: top-k ----------------
__global__ void k_topk(const float* __restrict__ pos, const float* __restrict__ noise,
                       int* __restrict__ nbr) {
    int warp = (blockIdx.x*blockDim.x + threadIdx.x) >> 5;
    int lane = threadIdx.x & 31;
    if (warp >= NN) return;
    int b = warp >> 9;
    int i = warp & (LL-1);
    const float* pb = pos + (size_t)b*LL*3;
    float px = pb[i*3], py = pb[i*3+1], pz = pb[i*3+2];
    const float* nrow = noise + ((size_t)b*LL + i)*LL;
    float vals[16];
#pragma unroll
    for (int t = 0; t < 16; t++) {
        int j = lane + (t<<5);
        float dx = pb[j*3]-px, dy = pb[j*3+1]-py, dz = pb[j*3+2]-pz;
        float d = sqrtf(dx*dx+dy*dy+dz*dz);
        vals[t] = -d + 3.0f*nrow[j];
    }
    for (int r = 0; r < NBR; r++) {
        float bv = vals[0]; int bt = 0;
#pragma unroll
        for (int t = 1; t < 16; t++)
            if (vals[t] > bv) { bv = vals[t]; bt = t; }
        int bj = lane + (bt<<5);
#pragma unroll
        for (int off = 16; off; off >>= 1) {
            float ov = __shfl_xor_sync(0xffffffffu, bv, off);
            int   oj = __shfl_xor_sync(0xffffffffu, bj, off);
            if (ov > bv || (ov == bv && oj < bj)) { bv = ov; bj = oj; }
        }
        if (lane == (bj & 31)) {
            int slot = bj >> 5;
#pragma unroll
            for (int t = 0; t < 16; t++)
                if (t == slot) vals[t] = -3.402823466e38f;
        }
        if (lane == 0) nbr[warp*NBR + r] = b*LL + bj;
    }
}

// ---------------- K: edge features ----------------
__global__ __launch_bounds__(256)
void k_edge(const float* __restrict__ pos, const float* __restrict__ R,
            const int* __restrict__ nbr, float* __restrict__ edge) {
    __shared__ float se[256*33];
    int e0 = blockIdx.x*256;
    int e = e0 + threadIdx.x;
    int n = e / NBR;
    int m = nbr[e];
    float dx = pos[m*3]-pos[n*3], dy = pos[m*3+1]-pos[n*3+1], dz = pos[m*3+2]-pos[n*3+2];
    float d = sqrtf(dx*dx+dy*dy+dz*dz);
    float* row = se + threadIdx.x*33;
#pragma unroll
    for (int t = 0; t < KER; t++) {
        float mu = (20.0f/15.0f)*t;
        float r = (d - mu)*0.8f;
        row[t] = expf(-r*r);
    }
    float inv = 1.0f/(d + 1e-8f);
    float u0 = dx*inv, u1 = dy*inv, u2 = dz*inv;
    const float* Rn = R + (size_t)n*9;
    const float* Rm = R + (size_t)m*9;
#pragma unroll
    for (int c = 0; c < 3; c++)
        row[16+c] = Rn[0*3+c]*u0 + Rn[1*3+c]*u1 + Rn[2*3+c]*u2;
#pragma unroll
    for (int c = 0; c < 3; c++)
#pragma unroll
        for (int dd = 0; dd < 3; dd++)
            row[19 + c*3 + dd] = Rn[0*3+c]*Rm[0*3+dd] + Rn[1*3+c]*Rm[1*3+dd] + Rn[2*3+c]*Rm[2*3+dd];
    row[28] = (float)(m - n);
    row[29] = 0.f; row[30] = 0.f; row[31] = 0.f;
    __syncthreads();
    float* dst = edge + (size_t)e0*EPAD;
    for (int i = threadIdx.x; i < 256*EPAD; i += 256)
        dst[i] = se[(i >> 5)*33 + (i & 31)];
}

// ---------------- h init ----------------
__global__ void k_hinit(const float* __restrict__ ew, const float* __restrict__ eb,
                        float* __restrict__ hi) {
    int c = threadIdx.x;
    float s = eb[c];
    for (int i = 0; i < 27; i++) s += ew[i*SIZE + c];
    hi[c] = s;
}

// ---------------- layer-0 qkv vector ----------------
__global__ void k_qkv0(const float* __restrict__ hi, const float* __restrict__ wq,
                       const float* __restrict__ wk, const float* __restrict__ wv,
                       float* __restrict__ qkv0) {
    int c = threadIdx.x;
    const float* W = (c < 128) ? (wq + c) : (c < 256) ? (wk + (c-128)) : (wv + (c-256));
    float s = 0.0f;
    for (int k = 0; k < 128; k++) s += hi[k]*W[k*128];
    qkv0[c] = s;
}

// ---------------- weight packs ----------------
__global__ void k_pack_tiles(const float* __restrict__ wq, const float* __restrict__ wk,
                             const float* __restrict__ wv, const float* __restrict__ wo,
                             const float* __restrict__ w1, const float* __restrict__ w2,
                             const float* __restrict__ w3, __nv_bfloat16* __restrict__ tiles) {
    int t = blockIdx.x;
    int l = t / 7, w = t % 7;
    const float* src;
    switch (w) {
        case 0: src = wq + (size_t)l*128*128; break;
        case 1: src = wk + (size_t)l*157*128; break;
        case 2: src = wv + (size_t)l*157*128; break;
        case 3: src = wo + (size_t)l*128*128; break;
        case 4: src = w1 + (size_t)l*128*128; break;
        case 5: src = w2 + (size_t)l*128*128; break;
        default: src = w3 + (size_t)l*128*128; break;
    }
    char* dh = (char*)(tiles + (size_t)t*32768);
    char* dl = dh + 32768;
    int e0 = blockIdx.y*2048;
    for (int e = e0 + threadIdx.x; e < e0 + 2048; e += 256) {
        int p = e & 127, k = e >> 7;
        float x = src[k*128 + p];
        __nv_bfloat16 h = __float2bfloat16(x);
        __nv_bfloat16 lo = __float2bfloat16(x - __bfloat162float(h));
        uint32_t off = tile_off(p, k);
        *(__nv_bfloat16*)(dh + off) = h;
        *(__nv_bfloat16*)(dl + off) = lo;
    }
}

__global__ void k_pack_conv(const float* __restrict__ pw, __nv_bfloat16* __restrict__ ct) {
    int t = blockIdx.x;
    int layer = t / 3, k = t % 3;
    const float* src = pw + (size_t)layer*128*128*3;
    char* dh = (char*)(ct + (size_t)t*32768);
    char* dl = dh + 32768;
    int e0 = blockIdx.y*2048;
    for (int e = e0 + threadIdx.x; e < e0 + 2048; e += 256) {
        int o = e >> 7, i = e & 127;
        float x = src[o*384 + i*3 + k];
        __nv_bfloat16 h = __float2bfloat16(x);
        __nv_bfloat16 lo = __float2bfloat16(x - __bfloat162float(h));
        uint32_t off = tile_off(o, i);
        *(__nv_bfloat16*)(dh + off) = h;
        *(__nv_bfloat16*)(dl + off) = lo;
    }
}

// ---------------- fused transformer layer (+ optional next-layer QKV) ----------------
// stages 0..3: wo(+res), w1(relu), w2(relu), w3(+res) -> h
// stages 4..6 (if qkv_out): next layer's wq,wk,wv on the new h -> qkv
__global__ __launch_bounds__(256, 2)
void k_layer(const float* __restrict__ opre, float* __restrict__ h,
             float* __restrict__ res, const __nv_bfloat16* __restrict__ lt,
             const __nv_bfloat16* __restrict__ ltn,
             const float* __restrict__ b1, const float* __restrict__ b2,
             const float* __restrict__ b3, const float* __restrict__ hvec,
             float* __restrict__ qkv_out) {
    extern __shared__ char dsm[];
    const uint32_t base = smem_u32(dsm);
    const uint32_t AH = base, AL = base + 32768, BB = base + 65536;

    int tid = threadIdx.x, lane = tid & 31, wid = tid >> 5;
    int row0 = blockIdx.x*128;
    int nstages = qkv_out ? 7 : 4;

    {
        const float* Arow = opre + (size_t)row0*128;
        for (int e = tid*4; e < 16384; e += 1024) {
            int r = e >> 7, k = e & 127;
            float4 a4 = *(const float4*)(Arow + r*128 + k);
            split_store(dsm, 32768, r, k,   a4.x, a4.y);
            split_store(dsm, 32768, r, k+2, a4.z, a4.w);
        }
    }

    int m_base = (wid & 3)*32, n_base = (wid >> 2)*64;
    int a_m  = (lane & 15);
    int a_kc = (lane >> 4);
    int b_r  = (lane & 7);
    int b_g  = (lane >> 3);
    int b_na = ((b_g >> 1) << 3) + b_r;
    int b_ka = (b_g & 1);
    int qr = lane >> 2, qc = (lane & 3)*2;

    for (int s = 0; s < nstages; s++) {
        const __nv_bfloat16* wtile = (s < 4) ? (lt + (size_t)(3 + s)*32768)
                                             : (ltn + (size_t)(s - 4)*32768);
        __syncthreads();
        {
            const uint4* src = (const uint4*)wtile;
            uint4* dst = (uint4*)(dsm + 65536);
            for (int i = tid; i < 2048; i += 256) dst[i] = src[i];
        }
        __syncthreads();

        float acc[2][8][4];
#pragma unroll
        for (int mt = 0; mt < 2; mt++)
#pragma unroll
            for (int nt = 0; nt < 8; nt++)
#pragma unroll
                for (int c = 0; c < 4; c++) acc[mt][nt][c] = 0.0f;

#pragma unroll
        for (int ks = 0; ks < 8; ks++) {
            int kc0 = ks*2;
            uint32_t ah[2][4], al[2][4];
#pragma unroll
            for (int mt = 0; mt < 2; mt++) {
                int m = m_base + mt*16 + a_m;
                ldm_x4(ah[mt], frag_addr(AH, m, kc0 + a_kc));
                ldm_x4(al[mt], frag_addr(AL, m, kc0 + a_kc));
            }
            uint32_t bb[4][4];
#pragma unroll
            for (int p = 0; p < 4; p++) {
                int n = n_base + p*16 + b_na;
                ldm_x4(bb[p], frag_addr(BB, n, kc0 + b_ka));
            }
#pragma unroll
            for (int mt = 0; mt < 2; mt++)
#pragma unroll
                for (int nt = 0; nt < 8; nt++) {
                    mma16816(acc[mt][nt], ah[mt], &bb[nt>>1][(nt&1)*2]);
                    mma16816(acc[mt][nt], al[mt], &bb[nt>>1][(nt&1)*2]);
                }
        }

        __syncthreads();
        {
            const uint4* src = (const uint4*)(wtile + 16384);
            uint4* dst = (uint4*)(dsm + 65536);
            for (int i = tid; i < 2048; i += 256) dst[i] = src[i];
        }
        __syncthreads();

#pragma unroll
        for (int ks = 0; ks < 8; ks++) {
            int kc0 = ks*2;
            uint32_t ah[2][4];
#pragma unroll
            for (int mt = 0; mt < 2; mt++) {
                int m = m_base + mt*16 + a_m;
                ldm_x4(ah[mt], frag_addr(AH, m, kc0 + a_kc));
            }
            uint32_t bb[4][4];
#pragma unroll
            for (int p = 0; p < 4; p++) {
                int n = n_base + p*16 + b_na;
                ldm_x4(bb[p], frag_addr(BB, n, kc0 + b_ka));
            }
#pragma unroll
            for (int mt = 0; mt < 2; mt++)
#pragma unroll
                for (int nt = 0; nt < 8; nt++)
                    mma16816(acc[mt][nt], ah[mt], &bb[nt>>1][(nt&1)*2]);
        }

        __syncthreads();

        const float* bias = (s == 1) ? b1 : (s == 2) ? b2 : (s == 3) ? b3 : nullptr;
#pragma unroll
        for (int mt = 0; mt < 2; mt++) {
#pragma unroll
            for (int hh = 0; hh < 2; hh++) {
                int rl = m_base + mt*16 + qr + hh*8;
                int row = row0 + rl;
#pragma unroll
                for (int nt = 0; nt < 8; nt++) {
                    int cc = n_base + nt*8 + qc;
                    float v0 = acc[mt][nt][hh*2+0];
                    float v1 = acc[mt][nt][hh*2+1];
                    if (s == 0) {
                        if (hvec) { v0 += hvec[cc]; v1 += hvec[cc+1]; }
                        else {
                            float2 h2 = *(const float2*)(h + (size_t)row*128 + cc);
                            v0 += h2.x; v1 += h2.y;
                        }
                        *(float2*)(res + (size_t)row*128 + cc) = make_float2(v0, v1);
                        split_store(dsm, 32768, rl, cc, v0, v1);
                    } else if (s < 3) {
                        v0 = fmaxf(v0 + bias[cc], 0.f);
                        v1 = fmaxf(v1 + bias[cc+1], 0.f);
                        split_store(dsm, 32768, rl, cc, v0, v1);
                    } else if (s == 3) {
                        float2 r2 = *(const float2*)(res + (size_t)row*128 + cc);
                        v0 += bias[cc]   + r2.x;
                        v1 += bias[cc+1] + r2.y;
                        *(float2*)(h + (size_t)row*128 + cc) = make_float2(v0, v1);
                        if (nstages > 4) split_store(dsm, 32768, rl, cc, v0, v1);
                    } else {
                        float* crow = qkv_out + (size_t)row*384 + (s-4)*128;
                        *(float2*)(crow + cc) = make_float2(v0, v1);
                    }
                }
            }
        }
    }
}

// ---------------- conv via tensor cores (fused 3-shift, R10 version) ----------------
__global__ __launch_bounds__(256, 2)
void k_conv_mma(const float* __restrict__ x, const __nv_bfloat16* __restrict__ ctiles,
                const float* __restrict__ bias, float* __restrict__ out, int Lin) {
    extern __shared__ char dsm[];
    const uint32_t base = smem_u32(dsm);
    const uint32_t AH = base, AL = base + 33792, BB = base + 67584;

    int tid = threadIdx.x, lane = tid & 31, wid = tid >> 5;
    int b = blockIdx.y, t0 = blockIdx.x*128;
    const float* xb = x + (size_t)b*128*Lin;

    {
        int c = tid >> 1, half = tid & 1;
        const float* xrow = xb + (size_t)c*Lin;
        for (int tp = half*66; tp < half*66 + 66; tp++) {
            int t = t0 + tp - 1;
            float v = (tp < 130 && t >= 0 && t < Lin) ? xrow[t] : 0.0f;
            __nv_bfloat16 hh = __float2bfloat16(v);
            __nv_bfloat16 ll = __float2bfloat16(v - __bfloat162float(hh));
            uint32_t off = tile_off(tp, c);
            *(__nv_bfloat16*)(dsm + off)         = hh;
            *(__nv_bfloat16*)(dsm + 33792 + off) = ll;
        }
    }

    int m_base = (wid & 3)*32, n_base = (wid >> 2)*64;
    float acc[2][8][4];
#pragma unroll
    for (int mt = 0; mt < 2; mt++)
#pragma unroll
        for (int nt = 0; nt < 8; nt++)
#pragma unroll
            for (int c = 0; c < 4; c++) acc[mt][nt][c] = 0.0f;

    int a_m  = (lane & 15);
    int a_kc = (lane >> 4);
    int b_r  = (lane & 7);
    int b_g  = (lane >> 3);
    int b_na = ((b_g >> 1) << 3) + b_r;
    int b_ka = (b_g & 1);

    for (int sh = 0; sh < 3; sh++) {
        const __nv_bfloat16* wt = ctiles + (size_t)sh*32768;
        __syncthreads();
        {
            const uint4* src = (const uint4*)wt;
            uint4* dst = (uint4*)(dsm + 67584);
            for (int i = tid; i < 2048; i += 256) dst[i] = src[i];
        }
        __syncthreads();
#pragma unroll
        for (int ks = 0; ks < 8; ks++) {
            int kc0 = ks*2;
            uint32_t ah[2][4], al[2][4];
#pragma unroll
            for (int mt = 0; mt < 2; mt++) {
                int m = m_base + mt*16 + a_m + sh;
                ldm_x4(ah[mt], frag_addr(AH, m, kc0 + a_kc));
                ldm_x4(al[mt], frag_addr(AL, m, kc0 + a_kc));
            }
            uint32_t bb[4][4];
#pragma unroll
            for (int p = 0; p < 4; p++) {
                int n = n_base + p*16 + b_na;
                ldm_x4(bb[p], frag_addr(BB, n, kc0 + b_ka));
            }
#pragma unroll
            for (int mt = 0; mt < 2; mt++)
#pragma unroll
                for (int nt = 0; nt < 8; nt++) {
                    mma16816(acc[mt][nt], ah[mt], &bb[nt>>1][(nt&1)*2]);
                    mma16816(acc[mt][nt], al[mt], &bb[nt>>1][(nt&1)*2]);
                }
        }
        __syncthreads();
        {
            const uint4* src = (const uint4*)(wt + 16384);
            uint4* dst = (uint4*)(dsm + 67584);
            for (int i = tid; i < 2048; i += 256) dst[i] = src[i];
        }
        __syncthreads();
#pragma unroll
        for (int ks = 0; ks < 8; ks++) {
            int kc0 = ks*2;
            uint32_t ah[2][4];
#pragma unroll
            for (int mt = 0; mt < 2; mt++) {
                int m = m_base + mt*16 + a_m + sh;
                ldm_x4(ah[mt], frag_addr(AH, m, kc0 + a_kc));
            }
            uint32_t bb[4][4];
#pragma unroll
            for (int p = 0; p < 4; p++) {
                int n = n_base + p*16 + b_na;
                ldm_x4(bb[p], frag_addr(BB, n, kc0 + b_ka));
            }
#pragma unroll
            for (int mt = 0; mt < 2; mt++)
#pragma unroll
                for (int nt = 0; nt < 8; nt++)
                    mma16816(acc[mt][nt], ah[mt], &bb[nt>>1][(nt&1)*2]);
        }
    }

    __syncthreads();
    float* ys = (float*)dsm;
    int qr = lane >> 2, qc = (lane & 3)*2;
#pragma unroll
    for (int mt = 0; mt < 2; mt++)
#pragma unroll
        for (int h = 0; h < 2; h++) {
            int m = m_base + mt*16 + h*8 + qr;
#pragma unroll
            for (int nt = 0; nt < 8; nt++) {
                int n0 = n_base + nt*8 + qc;
                ys[(size_t)n0*132 + m]     = acc[mt][nt][h*2+0];
                ys[(size_t)(n0+1)*132 + m] = acc[mt][nt][h*2+1];
            }
        }
    __syncthreads();

    {
        int o = tid >> 1, half = tid & 1;
        float bo = bias[o];
        const float* xrow = xb + (size_t)o*Lin;
        int Mrows = (Lin - t0 < 128) ? (Lin - t0) : 128;
        float* orow = out + ((size_t)b*128 + o)*(Lin/2) + (t0 >> 1);
        for (int t = half*64; t + 1 < Mrows && t < half*64 + 64; t += 2) {
            float y0 = ys[(size_t)o*132 + t]     + bo;
            float y1 = ys[(size_t)o*132 + t + 1] + bo;
            float z0 = xrow[t0+t]   + (y0 > 0.f ? y0 : 0.01f*y0);
            float z1 = xrow[t0+t+1] + (y1 > 0.f ? y1 : 0.01f*y1);
            orow[t >> 1] = fmaxf(z0, z1);
        }
    }
}

// ---------------- attention layer 0 ----------------
__global__ __launch_bounds__(256)
void k_attn0(const float* __restrict__ qkv0, const float* __restrict__ edge,
             const float* __restrict__ wk_e, const float* __restrict__ wv_e,
             float* __restrict__ opre) {
    __shared__ __align__(16) float sWk[EDGE*128];
    __shared__ __align__(16) float sWv[EDGE*128];
    __shared__ __align__(16) float sE[8][NBR*EPAD];

    int tid = threadIdx.x;
    for (int idx = tid; idx < EDGE*128; idx += 256) {
        sWk[idx] = wk_e[idx];
        sWv[idx] = wv_e[idx];
    }
    __syncthreads();

    int w = tid >> 5, lane = tid & 31;
    int n = blockIdx.x*8 + w;
    int d0 = lane*4;

    float4 q4 = *(const float4*)(qkv0 + d0);
    float4 v04 = *(const float4*)(qkv0 + 256 + d0);

    float qeh[EPAD];
#pragma unroll
    for (int e = 0; e < EDGE; e++) {
        float4 w4 = *(const float4*)(&sWk[e*128 + d0]);
        float p = q4.x*w4.x + q4.y*w4.y + q4.z*w4.z + q4.w*w4.w;
        p += __shfl_xor_sync(0xffffffffu, p, 1);
        p += __shfl_xor_sync(0xffffffffu, p, 2);
        qeh[e] = p;
    }
    qeh[29] = 0.f; qeh[30] = 0.f; qeh[31] = 0.f;

    {
        const float4* er4 = (const float4*)(edge + (size_t)n*NBR*EPAD);
        float4* sE4 = (float4*)sE[w];
        for (int idx = lane; idx < NBR*(EPAD/4); idx += 32) sE4[idx] = er4[idx];
    }
    __syncwarp();

    float logits[NBR];
#pragma unroll
    for (int j = 0; j < NBR; j++) {
        const float4* se = (const float4*)(sE[w] + j*EPAD);
        float e0 = 0.f, e1 = 0.f, e2 = 0.f, e3 = 0.f;
#pragma unroll
        for (int q = 0; q < 8; q++) {
            float4 s = se[q];
            e0 += s.x*qeh[q*4+0];
            e1 += s.y*qeh[q*4+1];
            e2 += s.z*qeh[q*4+2];
            e3 += s.w*qeh[q*4+3];
        }
        logits[j] = ((e0+e1)+(e2+e3))*0.25f;
    }

    float mx = logits[0];
#pragma unroll
    for (int j = 1; j < NBR; j++) mx = fmaxf(mx, logits[j]);
    float s = 0.0f;
#pragma unroll
    for (int j = 0; j < NBR; j++) { logits[j] = expf(logits[j]-mx); s += logits[j]; }
    float invs = 1.0f/s;

    float4 ae4[8];
#pragma unroll
    for (int q = 0; q < 8; q++) ae4[q] = make_float4(0.f,0.f,0.f,0.f);

#pragma unroll
    for (int j = 0; j < NBR; j++) {
        float a = logits[j]*invs;
        const float4* se = (const float4*)(sE[w] + j*EPAD);
#pragma unroll
        for (int q = 0; q < 8; q++) {
            float4 sv = se[q];
            ae4[q].x += a*sv.x; ae4[q].y += a*sv.y;
            ae4[q].z += a*sv.z; ae4[q].w += a*sv.w;
        }
    }
    float4 acc = v04;
#pragma unroll
    for (int q = 0; q < 8; q++) {
#pragma unroll
        for (int c2 = 0; c2 < 4; c2++) {
            int e = q*4 + c2;
            if (e >= EDGE) continue;
            float aev = (c2 == 0) ? ae4[q].x : (c2 == 1) ? ae4[q].y : (c2 == 2) ? ae4[q].z : ae4[q].w;
            float4 w4 = *(const float4*)(&sWv[e*128 + d0]);
            acc.x += aev*w4.x; acc.y += aev*w4.y;
            acc.z += aev*w4.z; acc.w += aev*w4.w;
        }
    }
    *(float4*)(opre + (size_t)n*SIZE + d0) = acc;
}

// ---------------- attention (layers 1+) ----------------
__global__ __launch_bounds__(256)
void k_attn(const float* __restrict__ qkv, const float* __restrict__ edge,
            const int* __restrict__ nbr,
            const float* __restrict__ wk_e, const float* __restrict__ wv_e,
            float* __restrict__ opre) {
    __shared__ __align__(16) float sWk[EDGE*128];
    __shared__ __align__(16) float sWv[EDGE*128];
    __shared__ __align__(16) float sE[8][NBR*EPAD];

    int tid = threadIdx.x;
    for (int idx = tid; idx < EDGE*128; idx += 256) {
        sWk[idx] = wk_e[idx];
        sWv[idx] = wv_e[idx];
    }
    __syncthreads();

    int w = tid >> 5, lane = tid & 31;
    int n = blockIdx.x*8 + w;
    int d0 = lane*4;

    float4 q4 = *(const float4*)(qkv + (size_t)n*384 + d0);

    float qeh[EPAD];
#pragma unroll
    for (int e = 0; e < EDGE; e++) {
        float4 w4 = *(const float4*)(&sWk[e*128 + d0]);
        float p = q4.x*w4.x + q4.y*w4.y + q4.z*w4.z + q4.w*w4.w;
        p += __shfl_xor_sync(0xffffffffu, p, 1);
        p += __shfl_xor_sync(0xffffffffu, p, 2);
        qeh[e] = p;
    }
    qeh[29] = 0.f; qeh[30] = 0.f; qeh[31] = 0.f;

    {
        const float4* er4 = (const float4*)(edge + (size_t)n*NBR*EPAD);
        float4* sE4 = (float4*)sE[w];
        for (int idx = lane; idx < NBR*(EPAD/4); idx += 32) sE4[idx] = er4[idx];
    }
    __syncwarp();

    const int* nb = nbr + n*NBR;
    int mj[NBR];
#pragma unroll
    for (int j = 0; j < NBR; j++) mj[j] = nb[j];

    float logits[NBR];
#pragma unroll
    for (int j = 0; j < NBR; j++) {
        float4 k4 = *(const float4*)(qkv + (size_t)mj[j]*384 + 128 + d0);
        float p = q4.x*k4.x + q4.y*k4.y + q4.z*k4.z + q4.w*k4.w;
        p += __shfl_xor_sync(0xffffffffu, p, 1);
        p += __shfl_xor_sync(0xffffffffu, p, 2);
        const float4* se = (const float4*)(sE[w] + j*EPAD);
        float e0 = 0.f, e1 = 0.f, e2 = 0.f, e3 = 0.f;
#pragma unroll
        for (int q = 0; q < 8; q++) {
            float4 s = se[q];
            e0 += s.x*qeh[q*4+0];
            e1 += s.y*qeh[q*4+1];
            e2 += s.z*qeh[q*4+2];
            e3 += s.w*qeh[q*4+3];
        }
        logits[j] = (p + ((e0+e1)+(e2+e3)))*0.25f;
    }

    float mx = logits[0];
#pragma unroll
    for (int j = 1; j < NBR; j++) mx = fmaxf(mx, logits[j]);
    float s = 0.0f;
#pragma unroll
    for (int j = 0; j < NBR; j++) { logits[j] = expf(logits[j]-mx); s += logits[j]; }
    float invs = 1.0f/s;

    float4 ae4[8];
#pragma unroll
    for (int q = 0; q < 8; q++) ae4[q] = make_float4(0.f,0.f,0.f,0.f);

    float4 acc = make_float4(0.f,0.f,0.f,0.f);
#pragma unroll
    for (int j = 0; j < NBR; j++) {
        float a = logits[j]*invs;
        float4 v4 = *(const float4*)(qkv + (size_t)mj[j]*384 + 256 + d0);
        acc.x += a*v4.x; acc.y += a*v4.y; acc.z += a*v4.z; acc.w += a*v4.w;
        const float4* se = (const float4*)(sE[w] + j*EPAD);
#pragma unroll
        for (int q = 0; q < 8; q++) {
            float4 sv = se[q];
            ae4[q].x += a*sv.x; ae4[q].y += a*sv.y;
            ae4[q].z += a*sv.z; ae4[q].w += a*sv.w;
        }
    }
#pragma unroll
    for (int q = 0; q < 8; q++) {
#pragma unroll
        for (int c2 = 0; c2 < 4; c2++) {
            int e = q*4 + c2;
            if (e >= EDGE) continue;
            float aev = (c2 == 0) ? ae4[q].x : (c2 == 1) ? ae4[q].y : (c2 == 2) ? ae4[q].z : ae4[q].w;
            float4 w4 = *(const float4*)(&sWv[e*128 + d0]);
            acc.x += aev*w4.x; acc.y += aev*w4.y;
            acc.z += aev*w4.z; acc.w += aev*w4.w;
        }
    }
    *(float4*)(opre + (size_t)n*SIZE + d0) = acc;
}

// ---------------- transpose ----------------
__global__ void k_transpose(const float* __restrict__ h, float* __restrict__ x) {
    int idx = blockIdx.x*blockDim.x + threadIdx.x;
    if (idx >= NN*SIZE) return;
    int t = idx & (LL-1);
    int c = (idx >> 9) & (SIZE-1);
    int b = idx >> 16;
    x[idx] = h[((size_t)(b*LL + t))*SIZE + c];
}

// ---------------- energy ----------------
__global__ void k_energy(const float* __restrict__ x, const float* __restrict__ ew,
                         const float* __restrict__ eb, float* __restrict__ out) {
    int b = blockIdx.x;
    int c = threadIdx.x;
    const float* xb = x + ((size_t)b*128 + c)*32;
    float s = 0.0f;
#pragma unroll
    for (int t = 0; t < 32; t++) s += xb[t];
    float v = s * ew[c];
    __shared__ float red[128];
    red[c] = v;
    __syncthreads();
    for (int st = 64; st; st >>= 1) {
        if (c < st) red[c] += red[c+st];
        __syncthreads();
    }
    if (c == 0) out[b] = red[0] + eb[0];
}

// ---------------- launch ----------------
extern "C" void kernel_launch(void* const* d_in, const int* in_sizes, int n_in,
                              void* d_out, int out_size) {
    const float* tert    = (const float*)d_in[0];
    const float* noise   = (const float*)d_in[3];
    const float* embed_w = (const float*)d_in[4];
    const float* embed_b = (const float*)d_in[5];
    const float* wq      = (const float*)d_in[6];
    const float* wk      = (const float*)d_in[7];
    const float* wv      = (const float*)d_in[8];
    const float* wo      = (const float*)d_in[9];
    const float* w1      = (const float*)d_in[10];
    const float* b1      = (const float*)d_in[11];
    const float* w2      = (const float*)d_in[12];
    const float* b2      = (const float*)d_in[13];
    const float* w3      = (const float*)d_in[14];
    const float* b3      = (const float*)d_in[15];
    const float* pool_w  = (const float*)d_in[16];
    const float* pool_b  = (const float*)d_in[17];
    const float* ew      = (const float*)d_in[18];
    const float* ebias   = (const float*)d_in[19];
    float* out = (float*)d_out;

    float *pos, *R, *edge, *h, *qkv, *opre, *res, *hi, *qkv0, *xa, *xb;
    int *nbrp;
    __nv_bfloat16 *tiles, *ctiles;
    cudaGetSymbolAddress((void**)&pos,  g_pos);
    cudaGetSymbolAddress((void**)&R,    g_R);
    cudaGetSymbolAddress((void**)&nbrp, g_nbr);
    cudaGetSymbolAddress((void**)&edge, g_edge);
    cudaGetSymbolAddress((void**)&h,    g_h);
    cudaGetSymbolAddress((void**)&qkv,  g_qkv);
    cudaGetSymbolAddress((void**)&opre, g_opre);
    cudaGetSymbolAddress((void**)&res,  g_res);
    cudaGetSymbolAddress((void**)&hi,   g_hinit);
    cudaGetSymbolAddress((void**)&qkv0, g_qkv0);
    cudaGetSymbolAddress((void**)&xa,   g_xa);
    cudaGetSymbolAddress((void**)&xb,   g_xb);
    cudaGetSymbolAddress((void**)&tiles,  g_wtiles);
    cudaGetSymbolAddress((void**)&ctiles, g_ctiles);

    const int GEMM_SMEM = 98304;
    const int CONV_SMEM = 100352;
    cudaFuncSetAttribute(k_layer,    cudaFuncAttributeMaxDynamicSharedMemorySize, GEMM_SMEM);
    cudaFuncSetAttribute(k_conv_mma, cudaFuncAttributeMaxDynamicSharedMemorySize, CONV_SMEM);

    k_frames<<<NN/256, 256>>>(tert, pos, R);
    k_topk<<<NN/8, 256>>>(pos, noise, nbrp);
    k_hinit<<<1, 128>>>(embed_w, embed_b, hi);
    k_edge<<<(NN*NBR)/256, 256>>>(pos, R, nbrp, edge);     // sampled (#4)
    k_pack_tiles<<<dim3(21,8), 256>>>(wq, wk, wv, wo, w1, w2, w3, tiles);
    k_pack_conv<<<dim3(12,8), 256>>>(pool_w, ctiles);
    k_qkv0<<<1, 384>>>(hi, wq, wk, wv, qkv0);

    // layer 0 (q/k/v identical across nodes) + next-layer QKV folded in
    {
        const float* wk_e = wk + 128*128;
        const float* wv_e = wv + 128*128;
        k_attn0<<<NN/8, 256>>>(qkv0, edge, wk_e, wv_e, opre);
        k_layer<<<NN/128, 256, GEMM_SMEM>>>(opre, h, res, tiles, tiles + 7*32768,
                                            b1, b2, b3, hi, qkv);
    }
    // layers 1..2 (QKV folded into previous k_layer)
    for (int l = 1; l < DEPTH; l++) {
        const float* wk_e = wk + (size_t)l*157*128 + 128*128;
        const float* wv_e = wv + (size_t)l*157*128 + 128*128;
        const __nv_bfloat16* lt  = tiles + (size_t)l*7*32768;
        const __nv_bfloat16* ltn = tiles + (size_t)(l+1)*7*32768;
        k_attn<<<NN/8, 256>>>(qkv, edge, nbrp, wk_e, wv_e, opre);
        k_layer<<<NN/128, 256, GEMM_SMEM>>>(opre, h, res, lt,
                                            (l < DEPTH-1) ? ltn : lt,
                                            b1 + l*128, b2 + l*128, b3 + l*128, nullptr,
                                            (l < DEPTH-1) ? qkv : nullptr);
    }

    k_transpose<<<NN*SIZE/256, 256>>>(h, xa);
    k_conv_mma<<<dim3(4, NB), 256, CONV_SMEM>>>(xa, ctiles + 0*3*32768, pool_b + 0,   xb, 512);
    k_conv_mma<<<dim3(2, NB), 256, CONV_SMEM>>>(xb, ctiles + 1*3*32768, pool_b + 128, xa, 256);
    k_conv_mma<<<dim3(1, NB), 256, CONV_SMEM>>>(xa, ctiles + 2*3*32768, pool_b + 256, xb, 128);
    k_conv_mma<<<dim3(1, NB), 256, CONV_SMEM>>>(xb, ctiles + 3*3*32768, pool_b + 384, xa, 64);
    k_energy<<<NB, 128>>>(xa, ew, ebias, out);
}

// round 13
// speedup vs baseline: 1.1419x; 1.0618x over previous
#include <cuda_runtime.h>
#include <cuda_bf16.h>
#include <cstdint>
#include <stdint.h>
#include <math.h>
#include <string.h>

// ---------------- problem constants ----------------
#define NB     64
#define LL     512
#define NN     (NB*LL)   // 32768
#define SIZE   128
#define NBR    15
#define KER    16
#define DEPTH  3
#define EDGE   29
#define EPAD   32

// ---------------- scratch ----------------
__device__ float g_pos[NN*3];
__device__ float g_R[NN*9];
__device__ int   g_nbr[NN*NBR];
__device__ float g_edge[(size_t)NN*NBR*EPAD];
__device__ float g_h[NN*SIZE];
__device__ float g_qkv[NN*384];
__device__ float g_opre[NN*SIZE];
__device__ float g_res[NN*SIZE];
__device__ float g_hinit[SIZE];
__device__ float g_qkv0[384];
__device__ float g_xa[(size_t)NB*SIZE*LL];          // node-major [b][t][c]
__device__ float g_xb[(size_t)NB*SIZE*(LL/2)];      // node-major [b][t][c]
__device__ __nv_bfloat16 g_wtiles[21*32768];
__device__ __nv_bfloat16 g_ctiles[12*32768];

// ---------------- helpers ----------------
__device__ __forceinline__ uint32_t smem_u32(const void* p) {
    uint32_t a;
    asm("{ .reg .u64 t; cvta.to.shared.u64 t, %1; cvt.u32.u64 %0, t; }" : "=r"(a) : "l"(p));
    return a;
}
__device__ __forceinline__ uint32_t tile_off(int row, int k) {
    return (uint32_t)(row*256 + ((((k>>3) ^ (row&7)) & 15) << 4) + (k&7)*2);
}
__device__ __forceinline__ uint32_t frag_addr(uint32_t base, int row, int kc) {
    return base + row*256 + (((kc ^ (row&7)) & 15) << 4);
}
__device__ __forceinline__ void ldm_x4(uint32_t* r, uint32_t addr) {
    asm volatile("ldmatrix.sync.aligned.m8n8.x4.shared.b16 {%0,%1,%2,%3}, [%4];"
        : "=r"(r[0]), "=r"(r[1]), "=r"(r[2]), "=r"(r[3]) : "r"(addr));
}
__device__ __forceinline__ void mma16816(float* c, const uint32_t* a, const uint32_t* b) {
    asm volatile("mma.sync.aligned.m16n8k16.row.col.f32.bf16.bf16.f32 "
        "{%0,%1,%2,%3}, {%4,%5,%6,%7}, {%8,%9}, {%0,%1,%2,%3};"
        : "+f"(c[0]), "+f"(c[1]), "+f"(c[2]), "+f"(c[3])
        : "r"(a[0]), "r"(a[1]), "r"(a[2]), "r"(a[3]), "r"(b[0]), "r"(b[1]));
}
__device__ __forceinline__ void split_store(char* dsmp, uint32_t loOfs, int row, int col, float v0, float v1) {
    __nv_bfloat162 hi = __floats2bfloat162_rn(v0, v1);
    float r0 = v0 - __bfloat162float(__low2bfloat16(hi));
    float r1 = v1 - __bfloat162float(__high2bfloat16(hi));
    __nv_bfloat162 lo = __floats2bfloat162_rn(r0, r1);
    uint32_t off = tile_off(row, col);
    *(__nv_bfloat162*)(dsmp + off)         = hi;
    *(__nv_bfloat162*)(dsmp + loOfs + off) = lo;
}

// ---------------- geometry ----------------
__device__ __forceinline__ float3 pos_at(const float* t, int i) {
    return make_float3(t[i*9+3], t[i*9+4], t[i*9+5]);
}
__device__ __forceinline__ float3 vsub(float3 a, float3 b){ return make_float3(a.x-b.x,a.y-b.y,a.z-b.z); }
__device__ __forceinline__ float3 vcross(float3 a, float3 b){
    return make_float3(a.y*b.z-a.z*b.y, a.z*b.x-a.x*b.z, a.x*b.y-a.y*b.x);
}
__device__ __forceinline__ float3 vnorm(float3 v){
    float n = sqrtf(v.x*v.x+v.y*v.y+v.z*v.z) + 1e-8f;
    return make_float3(v.x/n, v.y/n, v.z/n);
}

// ---------------- K: frames ----------------
__global__ void k_frames(const float* __restrict__ tert, float* __restrict__ pos, float* __restrict__ R) {
    int i = blockIdx.x*blockDim.x + threadIdx.x;
    if (i >= NN) return;
    float3 pi = pos_at(tert, i);
    pos[i*3+0]=pi.x; pos[i*3+1]=pi.y; pos[i*3+2]=pi.z;
    int t1 = (i >= 1) ? (i-1) : 0;
    int t2 = (i <= NN-2) ? i : (NN-2);
    float3 up = vnorm(vsub(pos_at(tert, t1+1), pos_at(tert, t1)));
    float3 un = vnorm(vsub(pos_at(tert, t2+1), pos_at(tert, t2)));
    float3 b  = vnorm(vsub(up, un));
    float3 nv = vnorm(vcross(up, un));
    float3 c3 = vcross(b, nv);
    float* r = R + (size_t)i*9;
    r[0]=b.x; r[1]=nv.x; r[2]=c3.x;
    r[3]=b.y; r[4]=nv.y; r[5]=c3.y;
    r[6]=b.z; r[7]=nv.z; r[8]=c3.z;
}

// ---------------- K: top-k ----------------
__global__ void k_topk(const float* __restrict__ pos, const float* __restrict__ noise,
                       int* __restrict__ nbr) {
    int warp = (blockIdx.x*blockDim.x + threadIdx.x) >> 5;
    int lane = threadIdx.x & 31;
    if (warp >= NN) return;
    int b = warp >> 9;
    int i = warp & (LL-1);
    const float* pb = pos + (size_t)b*LL*3;
    float px = pb[i*3], py = pb[i*3+1], pz = pb[i*3+2];
    const float* nrow = noise + ((size_t)b*LL + i)*LL;
    float vals[16];
#pragma unroll
    for (int t = 0; t < 16; t++) {
        int j = lane + (t<<5);
        float dx = pb[j*3]-px, dy = pb[j*3+1]-py, dz = pb[j*3+2]-pz;
        float d = sqrtf(dx*dx+dy*dy+dz*dz);
        vals[t] = -d + 3.0f*nrow[j];
    }
    for (int r = 0; r < NBR; r++) {
        float bv = vals[0]; int bt = 0;
#pragma unroll
        for (int t = 1; t < 16; t++)
            if (vals[t] > bv) { bv = vals[t]; bt = t; }
        int bj = lane + (bt<<5);
#pragma unroll
        for (int off = 16; off; off >>= 1) {
            float ov = __shfl_xor_sync(0xffffffffu, bv, off);
            int   oj = __shfl_xor_sync(0xffffffffu, bj, off);
            if (ov > bv || (ov == bv && oj < bj)) { bv = ov; bj = oj; }
        }
        if (lane == (bj & 31)) {
            int slot = bj >> 5;
#pragma unroll
            for (int t = 0; t < 16; t++)
                if (t == slot) vals[t] = -3.402823466e38f;
        }
        if (lane == 0) nbr[warp*NBR + r] = b*LL + bj;
    }
}

// ---------------- K: edge features ----------------
__global__ __launch_bounds__(256)
void k_edge(const float* __restrict__ pos, const float* __restrict__ R,
            const int* __restrict__ nbr, float* __restrict__ edge) {
    __shared__ float se[256*33];
    int e0 = blockIdx.x*256;
    int e = e0 + threadIdx.x;
    int n = e / NBR;
    int m = nbr[e];
    float dx = pos[m*3]-pos[n*3], dy = pos[m*3+1]-pos[n*3+1], dz = pos[m*3+2]-pos[n*3+2];
    float d = sqrtf(dx*dx+dy*dy+dz*dz);
    float* row = se + threadIdx.x*33;
#pragma unroll
    for (int t = 0; t < KER; t++) {
        float mu = (20.0f/15.0f)*t;
        float r = (d - mu)*0.8f;
        row[t] = expf(-r*r);
    }
    float inv = 1.0f/(d + 1e-8f);
    float u0 = dx*inv, u1 = dy*inv, u2 = dz*inv;
    const float* Rn = R + (size_t)n*9;
    const float* Rm = R + (size_t)m*9;
#pragma unroll
    for (int c = 0; c < 3; c++)
        row[16+c] = Rn[0*3+c]*u0 + Rn[1*3+c]*u1 + Rn[2*3+c]*u2;
#pragma unroll
    for (int c = 0; c < 3; c++)
#pragma unroll
        for (int dd = 0; dd < 3; dd++)
            row[19 + c*3 + dd] = Rn[0*3+c]*Rm[0*3+dd] + Rn[1*3+c]*Rm[1*3+dd] + Rn[2*3+c]*Rm[2*3+dd];
    row[28] = (float)(m - n);
    row[29] = 0.f; row[30] = 0.f; row[31] = 0.f;
    __syncthreads();
    float* dst = edge + (size_t)e0*EPAD;
    for (int i = threadIdx.x; i < 256*EPAD; i += 256)
        dst[i] = se[(i >> 5)*33 + (i & 31)];
}

// ---------------- h init ----------------
__global__ void k_hinit(const float* __restrict__ ew, const float* __restrict__ eb,
                        float* __restrict__ hi) {
    int c = threadIdx.x;
    float s = eb[c];
    for (int i = 0; i < 27; i++) s += ew[i*SIZE + c];
    hi[c] = s;
}

// ---------------- layer-0 qkv vector ----------------
__global__ void k_qkv0(const float* __restrict__ hi, const float* __restrict__ wq,
                       const float* __restrict__ wk, const float* __restrict__ wv,
                       float* __restrict__ qkv0) {
    int c = threadIdx.x;
    const float* W = (c < 128) ? (wq + c) : (c < 256) ? (wk + (c-128)) : (wv + (c-256));
    float s = 0.0f;
    for (int k = 0; k < 128; k++) s += hi[k]*W[k*128];
    qkv0[c] = s;
}

// ---------------- weight packs ----------------
__global__ void k_pack_tiles(const float* __restrict__ wq, const float* __restrict__ wk,
                             const float* __restrict__ wv, const float* __restrict__ wo,
                             const float* __restrict__ w1, const float* __restrict__ w2,
                             const float* __restrict__ w3, __nv_bfloat16* __restrict__ tiles) {
    int t = blockIdx.x;
    int l = t / 7, w = t % 7;
    const float* src;
    switch (w) {
        case 0: src = wq + (size_t)l*128*128; break;
        case 1: src = wk + (size_t)l*157*128; break;
        case 2: src = wv + (size_t)l*157*128; break;
        case 3: src = wo + (size_t)l*128*128; break;
        case 4: src = w1 + (size_t)l*128*128; break;
        case 5: src = w2 + (size_t)l*128*128; break;
        default: src = w3 + (size_t)l*128*128; break;
    }
    char* dh = (char*)(tiles + (size_t)t*32768);
    char* dl = dh + 32768;
    int e0 = blockIdx.y*2048;
    for (int e = e0 + threadIdx.x; e < e0 + 2048; e += 256) {
        int p = e & 127, k = e >> 7;
        float x = src[k*128 + p];
        __nv_bfloat16 h = __float2bfloat16(x);
        __nv_bfloat16 lo = __float2bfloat16(x - __bfloat162float(h));
        uint32_t off = tile_off(p, k);
        *(__nv_bfloat16*)(dh + off) = h;
        *(__nv_bfloat16*)(dl + off) = lo;
    }
}

__global__ void k_pack_conv(const float* __restrict__ pw, __nv_bfloat16* __restrict__ ct) {
    int t = blockIdx.x;
    int layer = t / 3, k = t % 3;
    const float* src = pw + (size_t)layer*128*128*3;
    char* dh = (char*)(ct + (size_t)t*32768);
    char* dl = dh + 32768;
    int e0 = blockIdx.y*2048;
    for (int e = e0 + threadIdx.x; e < e0 + 2048; e += 256) {
        int o = e >> 7, i = e & 127;
        float x = src[o*384 + i*3 + k];
        __nv_bfloat16 h = __float2bfloat16(x);
        __nv_bfloat16 lo = __float2bfloat16(x - __bfloat162float(h));
        uint32_t off = tile_off(o, i);
        *(__nv_bfloat16*)(dh + off) = h;
        *(__nv_bfloat16*)(dl + off) = lo;
    }
}

// ---------------- fused transformer layer (+ optional next-layer QKV) ----------------
__global__ __launch_bounds__(256, 2)
void k_layer(const float* __restrict__ opre, float* __restrict__ h,
             float* __restrict__ res, const __nv_bfloat16* __restrict__ lt,
             const __nv_bfloat16* __restrict__ ltn,
             const float* __restrict__ b1, const float* __restrict__ b2,
             const float* __restrict__ b3, const float* __restrict__ hvec,
             float* __restrict__ qkv_out) {
    extern __shared__ char dsm[];
    const uint32_t base = smem_u32(dsm);
    const uint32_t AH = base, AL = base + 32768, BB = base + 65536;

    int tid = threadIdx.x, lane = tid & 31, wid = tid >> 5;
    int row0 = blockIdx.x*128;
    int nstages = qkv_out ? 7 : 4;

    {
        const float* Arow = opre + (size_t)row0*128;
        for (int e = tid*4; e < 16384; e += 1024) {
            int r = e >> 7, k = e & 127;
            float4 a4 = *(const float4*)(Arow + r*128 + k);
            split_store(dsm, 32768, r, k,   a4.x, a4.y);
            split_store(dsm, 32768, r, k+2, a4.z, a4.w);
        }
    }

    int m_base = (wid & 3)*32, n_base = (wid >> 2)*64;
    int a_m  = (lane & 15);
    int a_kc = (lane >> 4);
    int b_r  = (lane & 7);
    int b_g  = (lane >> 3);
    int b_na = ((b_g >> 1) << 3) + b_r;
    int b_ka = (b_g & 1);
    int qr = lane >> 2, qc = (lane & 3)*2;

    for (int s = 0; s < nstages; s++) {
        const __nv_bfloat16* wtile = (s < 4) ? (lt + (size_t)(3 + s)*32768)
                                             : (ltn + (size_t)(s - 4)*32768);
        __syncthreads();
        {
            const uint4* src = (const uint4*)wtile;
            uint4* dst = (uint4*)(dsm + 65536);
            for (int i = tid; i < 2048; i += 256) dst[i] = src[i];
        }
        __syncthreads();

        float acc[2][8][4];
#pragma unroll
        for (int mt = 0; mt < 2; mt++)
#pragma unroll
            for (int nt = 0; nt < 8; nt++)
#pragma unroll
                for (int c = 0; c < 4; c++) acc[mt][nt][c] = 0.0f;

#pragma unroll
        for (int ks = 0; ks < 8; ks++) {
            int kc0 = ks*2;
            uint32_t ah[2][4], al[2][4];
#pragma unroll
            for (int mt = 0; mt < 2; mt++) {
                int m = m_base + mt*16 + a_m;
                ldm_x4(ah[mt], frag_addr(AH, m, kc0 + a_kc));
                ldm_x4(al[mt], frag_addr(AL, m, kc0 + a_kc));
            }
            uint32_t bb[4][4];
#pragma unroll
            for (int p = 0; p < 4; p++) {
                int n = n_base + p*16 + b_na;
                ldm_x4(bb[p], frag_addr(BB, n, kc0 + b_ka));
            }
#pragma unroll
            for (int mt = 0; mt < 2; mt++)
#pragma unroll
                for (int nt = 0; nt < 8; nt++) {
                    mma16816(acc[mt][nt], ah[mt], &bb[nt>>1][(nt&1)*2]);
                    mma16816(acc[mt][nt], al[mt], &bb[nt>>1][(nt&1)*2]);
                }
        }

        __syncthreads();
        {
            const uint4* src = (const uint4*)(wtile + 16384);
            uint4* dst = (uint4*)(dsm + 65536);
            for (int i = tid; i < 2048; i += 256) dst[i] = src[i];
        }
        __syncthreads();

#pragma unroll
        for (int ks = 0; ks < 8; ks++) {
            int kc0 = ks*2;
            uint32_t ah[2][4];
#pragma unroll
            for (int mt = 0; mt < 2; mt++) {
                int m = m_base + mt*16 + a_m;
                ldm_x4(ah[mt], frag_addr(AH, m, kc0 + a_kc));
            }
            uint32_t bb[4][4];
#pragma unroll
            for (int p = 0; p < 4; p++) {
                int n = n_base + p*16 + b_na;
                ldm_x4(bb[p], frag_addr(BB, n, kc0 + b_ka));
            }
#pragma unroll
            for (int mt = 0; mt < 2; mt++)
#pragma unroll
                for (int nt = 0; nt < 8; nt++)
                    mma16816(acc[mt][nt], ah[mt], &bb[nt>>1][(nt&1)*2]);
        }

        __syncthreads();

        const float* bias = (s == 1) ? b1 : (s == 2) ? b2 : (s == 3) ? b3 : nullptr;
#pragma unroll
        for (int mt = 0; mt < 2; mt++) {
#pragma unroll
            for (int hh = 0; hh < 2; hh++) {
                int rl = m_base + mt*16 + qr + hh*8;
                int row = row0 + rl;
#pragma unroll
                for (int nt = 0; nt < 8; nt++) {
                    int cc = n_base + nt*8 + qc;
                    float v0 = acc[mt][nt][hh*2+0];
                    float v1 = acc[mt][nt][hh*2+1];
                    if (s == 0) {
                        if (hvec) { v0 += hvec[cc]; v1 += hvec[cc+1]; }
                        else {
                            float2 h2 = *(const float2*)(h + (size_t)row*128 + cc);
                            v0 += h2.x; v1 += h2.y;
                        }
                        *(float2*)(res + (size_t)row*128 + cc) = make_float2(v0, v1);
                        split_store(dsm, 32768, rl, cc, v0, v1);
                    } else if (s < 3) {
                        v0 = fmaxf(v0 + bias[cc], 0.f);
                        v1 = fmaxf(v1 + bias[cc+1], 0.f);
                        split_store(dsm, 32768, rl, cc, v0, v1);
                    } else if (s == 3) {
                        float2 r2 = *(const float2*)(res + (size_t)row*128 + cc);
                        v0 += bias[cc]   + r2.x;
                        v1 += bias[cc+1] + r2.y;
                        *(float2*)(h + (size_t)row*128 + cc) = make_float2(v0, v1);
                        if (nstages > 4) split_store(dsm, 32768, rl, cc, v0, v1);
                    } else {
                        float* crow = qkv_out + (size_t)row*384 + (s-4)*128;
                        *(float2*)(crow + cc) = make_float2(v0, v1);
                    }
                }
            }
        }
    }
}

// ---------------- conv via tensor cores (node-major I/O, coalesced) ----------------
// x: [b][Lin][128]  -> out: [b][Lin/2][128]
__global__ __launch_bounds__(256, 2)
void k_conv_mma(const float* __restrict__ x, const __nv_bfloat16* __restrict__ ctiles,
                const float* __restrict__ bias, float* __restrict__ out, int Lin) {
    extern __shared__ char dsm[];
    const uint32_t base = smem_u32(dsm);
    const uint32_t AH = base, AL = base + 33792, BB = base + 67584;

    int tid = threadIdx.x, lane = tid & 31, wid = tid >> 5;
    int b = blockIdx.y, t0 = blockIdx.x*128;
    const float* xb = x + (size_t)b*Lin*128;

    // stage X tile [tp 0..131][c 0..127] hi/lo, t = t0 + tp - 1; coalesced (c fastest)
    for (int idx = tid; idx < 132*64; idx += 256) {
        int tp = idx >> 6, cp = (idx & 63)*2;
        int t = t0 + tp - 1;
        float2 v = make_float2(0.f, 0.f);
        if (tp < 130 && t >= 0 && t < Lin)
            v = *(const float2*)(xb + (size_t)t*128 + cp);
        split_store(dsm, 33792, tp, cp, v.x, v.y);
    }

    int m_base = (wid & 3)*32, n_base = (wid >> 2)*64;
    float acc[2][8][4];
#pragma unroll
    for (int mt = 0; mt < 2; mt++)
#pragma unroll
        for (int nt = 0; nt < 8; nt++)
#pragma unroll
            for (int c = 0; c < 4; c++) acc[mt][nt][c] = 0.0f;

    int a_m  = (lane & 15);
    int a_kc = (lane >> 4);
    int b_r  = (lane & 7);
    int b_g  = (lane >> 3);
    int b_na = ((b_g >> 1) << 3) + b_r;
    int b_ka = (b_g & 1);

    for (int sh = 0; sh < 3; sh++) {
        const __nv_bfloat16* wt = ctiles + (size_t)sh*32768;
        __syncthreads();
        {
            const uint4* src = (const uint4*)wt;
            uint4* dst = (uint4*)(dsm + 67584);
            for (int i = tid; i < 2048; i += 256) dst[i] = src[i];
        }
        __syncthreads();
#pragma unroll
        for (int ks = 0; ks < 8; ks++) {
            int kc0 = ks*2;
            uint32_t ah[2][4], al[2][4];
#pragma unroll
            for (int mt = 0; mt < 2; mt++) {
                int m = m_base + mt*16 + a_m + sh;
                ldm_x4(ah[mt], frag_addr(AH, m, kc0 + a_kc));
                ldm_x4(al[mt], frag_addr(AL, m, kc0 + a_kc));
            }
            uint32_t bb[4][4];
#pragma unroll
            for (int p = 0; p < 4; p++) {
                int n = n_base + p*16 + b_na;
                ldm_x4(bb[p], frag_addr(BB, n, kc0 + b_ka));
            }
#pragma unroll
            for (int mt = 0; mt < 2; mt++)
#pragma unroll
                for (int nt = 0; nt < 8; nt++) {
                    mma16816(acc[mt][nt], ah[mt], &bb[nt>>1][(nt&1)*2]);
                    mma16816(acc[mt][nt], al[mt], &bb[nt>>1][(nt&1)*2]);
                }
        }
        __syncthreads();
        {
            const uint4* src = (const uint4*)(wt + 16384);
            uint4* dst = (uint4*)(dsm + 67584);
            for (int i = tid; i < 2048; i += 256) dst[i] = src[i];
        }
        __syncthreads();
#pragma unroll
        for (int ks = 0; ks < 8; ks++) {
            int kc0 = ks*2;
            uint32_t ah[2][4];
#pragma unroll
            for (int mt = 0; mt < 2; mt++) {
                int m = m_base + mt*16 + a_m + sh;
                ldm_x4(ah[mt], frag_addr(AH, m, kc0 + a_kc));
            }
            uint32_t bb[4][4];
#pragma unroll
            for (int p = 0; p < 4; p++) {
                int n = n_base + p*16 + b_na;
                ldm_x4(bb[p], frag_addr(BB, n, kc0 + b_ka));
            }
#pragma unroll
            for (int mt = 0; mt < 2; mt++)
#pragma unroll
                for (int nt = 0; nt < 8; nt++)
                    mma16816(acc[mt][nt], ah[mt], &bb[nt>>1][(nt&1)*2]);
        }
    }

    __syncthreads();
    float* ys = (float*)dsm;   // [o][t] stride 132
    int qr = lane >> 2, qc = (lane & 3)*2;
#pragma unroll
    for (int mt = 0; mt < 2; mt++)
#pragma unroll
        for (int h = 0; h < 2; h++) {
            int m = m_base + mt*16 + h*8 + qr;
#pragma unroll
            for (int nt = 0; nt < 8; nt++) {
                int n0 = n_base + nt*8 + qc;
                ys[(size_t)n0*132 + m]     = acc[mt][nt][h*2+0];
                ys[(size_t)(n0+1)*132 + m] = acc[mt][nt][h*2+1];
            }
        }
    __syncthreads();

    // epilogue: bias + leaky + residual + maxpool2; coalesced (o fastest)
    {
        int Mrows = (Lin - t0 < 128) ? (Lin - t0) : 128;
        int nout = (Mrows >> 1)*128;
        for (int idx = tid; idx < nout; idx += 256) {
            int o = idx & 127, th = idx >> 7;
            int t = 2*th;
            float bo = bias[o];
            float y0 = ys[(size_t)o*132 + t]     + bo;
            float y1 = ys[(size_t)o*132 + t + 1] + bo;
            float x0 = xb[(size_t)(t0 + t)*128 + o];
            float x1 = xb[(size_t)(t0 + t + 1)*128 + o];
            float z0 = x0 + (y0 > 0.f ? y0 : 0.01f*y0);
            float z1 = x1 + (y1 > 0.f ? y1 : 0.01f*y1);
            out[((size_t)b*(Lin>>1) + (t0>>1) + th)*128 + o] = fmaxf(z0, z1);
        }
    }
}

// ---------------- attention layer 0 ----------------
__global__ __launch_bounds__(256)
void k_attn0(const float* __restrict__ qkv0, const float* __restrict__ edge,
             const float* __restrict__ wk_e, const float* __restrict__ wv_e,
             float* __restrict__ opre) {
    __shared__ __align__(16) float sWk[EDGE*128];
    __shared__ __align__(16) float sWv[EDGE*128];
    __shared__ __align__(16) float sE[8][NBR*EPAD];

    int tid = threadIdx.x;
    for (int idx = tid; idx < EDGE*128; idx += 256) {
        sWk[idx] = wk_e[idx];
        sWv[idx] = wv_e[idx];
    }
    __syncthreads();

    int w = tid >> 5, lane = tid & 31;
    int n = blockIdx.x*8 + w;
    int d0 = lane*4;

    float4 q4 = *(const float4*)(qkv0 + d0);
    float4 v04 = *(const float4*)(qkv0 + 256 + d0);

    float qeh[EPAD];
#pragma unroll
    for (int e = 0; e < EDGE; e++) {
        float4 w4 = *(const float4*)(&sWk[e*128 + d0]);
        float p = q4.x*w4.x + q4.y*w4.y + q4.z*w4.z + q4.w*w4.w;
        p += __shfl_xor_sync(0xffffffffu, p, 1);
        p += __shfl_xor_sync(0xffffffffu, p, 2);
        qeh[e] = p;
    }
    qeh[29] = 0.f; qeh[30] = 0.f; qeh[31] = 0.f;

    {
        const float4* er4 = (const float4*)(edge + (size_t)n*NBR*EPAD);
        float4* sE4 = (float4*)sE[w];
        for (int idx = lane; idx < NBR*(EPAD/4); idx += 32) sE4[idx] = er4[idx];
    }
    __syncwarp();

    float logits[NBR];
#pragma unroll
    for (int j = 0; j < NBR; j++) {
        const float4* se = (const float4*)(sE[w] + j*EPAD);
        float e0 = 0.f, e1 = 0.f, e2 = 0.f, e3 = 0.f;
#pragma unroll
        for (int q = 0; q < 8; q++) {
            float4 s = se[q];
            e0 += s.x*qeh[q*4+0];
            e1 += s.y*qeh[q*4+1];
            e2 += s.z*qeh[q*4+2];
            e3 += s.w*qeh[q*4+3];
        }
        logits[j] = ((e0+e1)+(e2+e3))*0.25f;
    }

    float mx = logits[0];
#pragma unroll
    for (int j = 1; j < NBR; j++) mx = fmaxf(mx, logits[j]);
    float s = 0.0f;
#pragma unroll
    for (int j = 0; j < NBR; j++) { logits[j] = expf(logits[j]-mx); s += logits[j]; }
    float invs = 1.0f/s;

    float4 ae4[8];
#pragma unroll
    for (int q = 0; q < 8; q++) ae4[q] = make_float4(0.f,0.f,0.f,0.f);

#pragma unroll
    for (int j = 0; j < NBR; j++) {
        float a = logits[j]*invs;
        const float4* se = (const float4*)(sE[w] + j*EPAD);
#pragma unroll
        for (int q = 0; q < 8; q++) {
            float4 sv = se[q];
            ae4[q].x += a*sv.x; ae4[q].y += a*sv.y;
            ae4[q].z += a*sv.z; ae4[q].w += a*sv.w;
        }
    }
    float4 acc = v04;
#pragma unroll
    for (int q = 0; q < 8; q++) {
#pragma unroll
        for (int c2 = 0; c2 < 4; c2++) {
            int e = q*4 + c2;
            if (e >= EDGE) continue;
            float aev = (c2 == 0) ? ae4[q].x : (c2 == 1) ? ae4[q].y : (c2 == 2) ? ae4[q].z : ae4[q].w;
            float4 w4 = *(const float4*)(&sWv[e*128 + d0]);
            acc.x += aev*w4.x; acc.y += aev*w4.y;
            acc.z += aev*w4.z; acc.w += aev*w4.w;
        }
    }
    *(float4*)(opre + (size_t)n*SIZE + d0) = acc;
}

// ---------------- attention (layers 1+) ----------------
__global__ __launch_bounds__(256)
void k_attn(const float* __restrict__ qkv, const float* __restrict__ edge,
            const int* __restrict__ nbr,
            const float* __restrict__ wk_e, const float* __restrict__ wv_e,
            float* __restrict__ opre) {
    __shared__ __align__(16) float sWk[EDGE*128];
    __shared__ __align__(16) float sWv[EDGE*128];
    __shared__ __align__(16) float sE[8][NBR*EPAD];

    int tid = threadIdx.x;
    for (int idx = tid; idx < EDGE*128; idx += 256) {
        sWk[idx] = wk_e[idx];
        sWv[idx] = wv_e[idx];
    }
    __syncthreads();

    int w = tid >> 5, lane = tid & 31;
    int n = blockIdx.x*8 + w;
    int d0 = lane*4;

    float4 q4 = *(const float4*)(qkv + (size_t)n*384 + d0);

    float qeh[EPAD];
#pragma unroll
    for (int e = 0; e < EDGE; e++) {
        float4 w4 = *(const float4*)(&sWk[e*128 + d0]);
        float p = q4.x*w4.x + q4.y*w4.y + q4.z*w4.z + q4.w*w4.w;
        p += __shfl_xor_sync(0xffffffffu, p, 1);
        p += __shfl_xor_sync(0xffffffffu, p, 2);
        qeh[e] = p;
    }
    qeh[29] = 0.f; qeh[30] = 0.f; qeh[31] = 0.f;

    {
        const float4* er4 = (const float4*)(edge + (size_t)n*NBR*EPAD);
        float4* sE4 = (float4*)sE[w];
        for (int idx = lane; idx < NBR*(EPAD/4); idx += 32) sE4[idx] = er4[idx];
    }
    __syncwarp();

    const int* nb = nbr + n*NBR;
    int mj[NBR];
#pragma unroll
    for (int j = 0; j < NBR; j++) mj[j] = nb[j];

    float logits[NBR];
#pragma unroll
    for (int j = 0; j < NBR; j++) {
        float4 k4 = *(const float4*)(qkv + (size_t)mj[j]*384 + 128 + d0);
        float p = q4.x*k4.x + q4.y*k4.y + q4.z*k4.z + q4.w*k4.w;
        p += __shfl_xor_sync(0xffffffffu, p, 1);
        p += __shfl_xor_sync(0xffffffffu, p, 2);
        const float4* se = (const float4*)(sE[w] + j*EPAD);
        float e0 = 0.f, e1 = 0.f, e2 = 0.f, e3 = 0.f;
#pragma unroll
        for (int q = 0; q < 8; q++) {
            float4 s = se[q];
            e0 += s.x*qeh[q*4+0];
            e1 += s.y*qeh[q*4+1];
            e2 += s.z*qeh[q*4+2];
            e3 += s.w*qeh[q*4+3];
        }
        logits[j] = (p + ((e0+e1)+(e2+e3)))*0.25f;
    }

    float mx = logits[0];
#pragma unroll
    for (int j = 1; j < NBR; j++) mx = fmaxf(mx, logits[j]);
    float s = 0.0f;
#pragma unroll
    for (int j = 0; j < NBR; j++) { logits[j] = expf(logits[j]-mx); s += logits[j]; }
    float invs = 1.0f/s;

    float4 ae4[8];
#pragma unroll
    for (int q = 0; q < 8; q++) ae4[q] = make_float4(0.f,0.f,0.f,0.f);

    float4 acc = make_float4(0.f,0.f,0.f,0.f);
#pragma unroll
    for (int j = 0; j < NBR; j++) {
        float a = logits[j]*invs;
        float4 v4 = *(const float4*)(qkv + (size_t)mj[j]*384 + 256 + d0);
        acc.x += a*v4.x; acc.y += a*v4.y; acc.z += a*v4.z; acc.w += a*v4.w;
        const float4* se = (const float4*)(sE[w] + j*EPAD);
#pragma unroll
        for (int q = 0; q < 8; q++) {
            float4 sv = se[q];
            ae4[q].x += a*sv.x; ae4[q].y += a*sv.y;
            ae4[q].z += a*sv.z; ae4[q].w += a*sv.w;
        }
    }
#pragma unroll
    for (int q = 0; q < 8; q++) {
#pragma unroll
        for (int c2 = 0; c2 < 4; c2++) {
            int e = q*4 + c2;
            if (e >= EDGE) continue;
            float aev = (c2 == 0) ? ae4[q].x : (c2 == 1) ? ae4[q].y : (c2 == 2) ? ae4[q].z : ae4[q].w;
            float4 w4 = *(const float4*)(&sWv[e*128 + d0]);
            acc.x += aev*w4.x; acc.y += aev*w4.y;
            acc.z += aev*w4.z; acc.w += aev*w4.w;
        }
    }
    *(float4*)(opre + (size_t)n*SIZE + d0) = acc;
}

// ---------------- energy (node-major input [b][32][128]) ----------------
__global__ void k_energy(const float* __restrict__ x, const float* __restrict__ ew,
                         const float* __restrict__ eb, float* __restrict__ out) {
    int b = blockIdx.x;
    int c = threadIdx.x;
    const float* xb = x + (size_t)b*32*128 + c;
    float s = 0.0f;
#pragma unroll
    for (int t = 0; t < 32; t++) s += xb[t*128];
    float v = s * ew[c];
    __shared__ float red[128];
    red[c] = v;
    __syncthreads();
    for (int st = 64; st; st >>= 1) {
        if (c < st) red[c] += red[c+st];
        __syncthreads();
    }
    if (c == 0) out[b] = red[0] + eb[0];
}

// ---------------- launch ----------------
extern "C" void kernel_launch(void* const* d_in, const int* in_sizes, int n_in,
                              void* d_out, int out_size) {
    const float* tert    = (const float*)d_in[0];
    const float* noise   = (const float*)d_in[3];
    const float* embed_w = (const float*)d_in[4];
    const float* embed_b = (const float*)d_in[5];
    const float* wq      = (const float*)d_in[6];
    const float* wk      = (const float*)d_in[7];
    const float* wv      = (const float*)d_in[8];
    const float* wo      = (const float*)d_in[9];
    const float* w1      = (const float*)d_in[10];
    const float* b1      = (const float*)d_in[11];
    const float* w2      = (const float*)d_in[12];
    const float* b2      = (const float*)d_in[13];
    const float* w3      = (const float*)d_in[14];
    const float* b3      = (const float*)d_in[15];
    const float* pool_w  = (const float*)d_in[16];
    const float* pool_b  = (const float*)d_in[17];
    const float* ew      = (const float*)d_in[18];
    const float* ebias   = (const float*)d_in[19];
    float* out = (float*)d_out;

    float *pos, *R, *edge, *h, *qkv, *opre, *res, *hi, *qkv0, *xa, *xb;
    int *nbrp;
    __nv_bfloat16 *tiles, *ctiles;
    cudaGetSymbolAddress((void**)&pos,  g_pos);
    cudaGetSymbolAddress((void**)&R,    g_R);
    cudaGetSymbolAddress((void**)&nbrp, g_nbr);
    cudaGetSymbolAddress((void**)&edge, g_edge);
    cudaGetSymbolAddress((void**)&h,    g_h);
    cudaGetSymbolAddress((void**)&qkv,  g_qkv);
    cudaGetSymbolAddress((void**)&opre, g_opre);
    cudaGetSymbolAddress((void**)&res,  g_res);
    cudaGetSymbolAddress((void**)&hi,   g_hinit);
    cudaGetSymbolAddress((void**)&qkv0, g_qkv0);
    cudaGetSymbolAddress((void**)&xa,   g_xa);
    cudaGetSymbolAddress((void**)&xb,   g_xb);
    cudaGetSymbolAddress((void**)&tiles,  g_wtiles);
    cudaGetSymbolAddress((void**)&ctiles, g_ctiles);

    const int GEMM_SMEM = 98304;
    const int CONV_SMEM = 100352;
    cudaFuncSetAttribute(k_layer,    cudaFuncAttributeMaxDynamicSharedMemorySize, GEMM_SMEM);
    cudaFuncSetAttribute(k_conv_mma, cudaFuncAttributeMaxDynamicSharedMemorySize, CONV_SMEM);

    k_frames<<<NN/256, 256>>>(tert, pos, R);
    k_topk<<<NN/8, 256>>>(pos, noise, nbrp);
    k_hinit<<<1, 128>>>(embed_w, embed_b, hi);
    k_edge<<<(NN*NBR)/256, 256>>>(pos, R, nbrp, edge);     // sampled (#4)
    k_pack_tiles<<<dim3(21,8), 256>>>(wq, wk, wv, wo, w1, w2, w3, tiles);
    k_pack_conv<<<dim3(12,8), 256>>>(pool_w, ctiles);
    k_qkv0<<<1, 384>>>(hi, wq, wk, wv, qkv0);

    // layer 0 (q/k/v identical across nodes) + next-layer QKV folded in
    {
        const float* wk_e = wk + 128*128;
        const float* wv_e = wv + 128*128;
        k_attn0<<<NN/8, 256>>>(qkv0, edge, wk_e, wv_e, opre);
        k_layer<<<NN/128, 256, GEMM_SMEM>>>(opre, h, res, tiles, tiles + 7*32768,
                                            b1, b2, b3, hi, qkv);
    }
    // layers 1..2 (QKV folded into previous k_layer)
    for (int l = 1; l < DEPTH; l++) {
        const float* wk_e = wk + (size_t)l*157*128 + 128*128;
        const float* wv_e = wv + (size_t)l*157*128 + 128*128;
        const __nv_bfloat16* lt  = tiles + (size_t)l*7*32768;
        const __nv_bfloat16* ltn = tiles + (size_t)(l+1)*7*32768;
        k_attn<<<NN/8, 256>>>(qkv, edge, nbrp, wk_e, wv_e, opre);
        k_layer<<<NN/128, 256, GEMM_SMEM>>>(opre, h, res, lt,
                                            (l < DEPTH-1) ? ltn : lt,
                                            b1 + l*128, b2 + l*128, b3 + l*128, nullptr,
                                            (l < DEPTH-1) ? qkv : nullptr);
    }

    // conv head: node-major, transpose eliminated (layer 1 reads h directly)
    k_conv_mma<<<dim3(4, NB), 256, CONV_SMEM>>>(h,  ctiles + 0*3*32768, pool_b + 0,   xb, 512);
    k_conv_mma<<<dim3(2, NB), 256, CONV_SMEM>>>(xb, ctiles + 1*3*32768, pool_b + 128, xa, 256);
    k_conv_mma<<<dim3(1, NB), 256, CONV_SMEM>>>(xa, ctiles + 2*3*32768, pool_b + 256, xb, 128);
    k_conv_mma<<<dim3(1, NB), 256, CONV_SMEM>>>(xb, ctiles + 3*3*32768, pool_b + 384, xa, 64);
    k_energy<<<NB, 128>>>(xa, ew, ebias, out);
}